// round 9
// baseline (speedup 1.0000x reference)
#include <cuda_runtime.h>
#include <cuda_fp16.h>
#include <math.h>

#define NMAX 50000
#define EMAX 800000
#define ETMAX (EMAX + NMAX)

// ---------------- scratch (device globals) -----------------------------------
__device__ __half g_h1h[NMAX * 256];     // GAT1 features fp16 (gather payload)
__device__ float g_asrc1[NMAX * 8];
__device__ float g_adst1[NMAX * 8];
__device__ __half g_h2h[NMAX * 16];      // GAT2 features fp16
__device__ float g_asrc2[NMAX];
__device__ float g_adst2[NMAX];
__device__ __half g_gh[NMAX * 16];       // GCN per-src message fp16
__device__ int   g_degi[NMAX];
__device__ int   g_cursor[NMAX];
__device__ int   g_rowptr[NMAX + 1];
__device__ int   g_esrc[ETMAX];
__device__ float2 g_xsp[NMAX * 128];     // x split into (hi,lo) tf32 pairs
__device__ float2 g_wsp[128 * 256];      // W1 split

__device__ __forceinline__ float lrelu(float x) { return x > 0.f ? x : 0.2f * x; }
__device__ __forceinline__ float eluf(float x) { return x > 0.f ? x : expm1f(x); }

// ---------------- CSR build ---------------------------------------------------
__global__ void k_deg(const int* __restrict__ ei, int E, int N, int* __restrict__ degi) {
    int e = blockIdx.x * blockDim.x + threadIdx.x;
    int ET = E + N;
    if (e >= ET) return;
    int d = (e < E) ? ei[E + e] : e - E;
    atomicAdd(&degi[d], 1);
}

__global__ void k_scan(const int* __restrict__ degi, int* __restrict__ rowptr,
                       int N, int ET) {
    __shared__ int sh[1024];
    int t = threadIdx.x;
    int chunk = (N + 1023) / 1024;
    int start = t * chunk;
    int end = min(start + chunk, N);
    int sum = 0;
    for (int i = start; i < end; i++) sum += degi[i];
    sh[t] = sum;
    __syncthreads();
    for (int off = 1; off < 1024; off <<= 1) {
        int v = (t >= off) ? sh[t - off] : 0;
        __syncthreads();
        sh[t] += v;
        __syncthreads();
    }
    int run = (t == 0) ? 0 : sh[t - 1];
    for (int i = start; i < end; i++) { rowptr[i] = run; run += degi[i]; }
    if (t == 1023) rowptr[N] = ET;
}

__global__ void k_fill(const int* __restrict__ ei, int E, int N,
                       const int* __restrict__ rowptr, int* __restrict__ cursor,
                       int* __restrict__ esrc) {
    int e = blockIdx.x * blockDim.x + threadIdx.x;
    int ET = E + N;
    if (e >= ET) return;
    int s, d;
    if (e < E) { s = ei[e]; d = ei[E + e]; } else { s = d = e - E; }
    int pos = rowptr[d] + atomicAdd(&cursor[d], 1);
    esrc[pos] = s;
}

// ---------------- tf32 helpers ------------------------------------------------
__device__ __forceinline__ float2 tf32split2(float x) {
    unsigned u;
    asm("cvt.rna.tf32.f32 %0, %1;" : "=r"(u) : "f"(x));
    float hi = __uint_as_float(u);
    float r = x - hi;
    unsigned ul;
    asm("cvt.rna.tf32.f32 %0, %1;" : "=r"(ul) : "f"(r));
    return make_float2(hi, __uint_as_float(ul));
}

__device__ __forceinline__ void mma_tf32(float* d, const unsigned* a, const unsigned* b) {
    asm volatile("mma.sync.aligned.m16n8k8.row.col.f32.tf32.tf32.f32 "
                 "{%0,%1,%2,%3}, {%4,%5,%6,%7}, {%8,%9}, {%0,%1,%2,%3};"
                 : "+f"(d[0]), "+f"(d[1]), "+f"(d[2]), "+f"(d[3])
                 : "r"(a[0]), "r"(a[1]), "r"(a[2]), "r"(a[3]),
                   "r"(b[0]), "r"(b[1]));
}

__device__ __forceinline__ void cpasync16(void* dst, const void* src) {
    unsigned d = (unsigned)__cvta_generic_to_shared(dst);
    asm volatile("cp.async.cg.shared.global [%0], [%1], 16;" :: "r"(d), "l"(src));
}

// ---------------- split pass: f32 -> interleaved (hi,lo) ----------------------
__global__ void k_split(const float* __restrict__ src, float2* __restrict__ dst,
                        int total4) {
    int i = blockIdx.x * blockDim.x + threadIdx.x;
    if (i >= total4) return;
    float4 v = reinterpret_cast<const float4*>(src)[i];
    float2 o0 = tf32split2(v.x), o1 = tf32split2(v.y);
    float2 o2 = tf32split2(v.z), o3 = tf32split2(v.w);
    float4* d = reinterpret_cast<float4*>(dst + (size_t)i * 4);
    d[0] = make_float4(o0.x, o0.y, o1.x, o1.y);
    d[1] = make_float4(o2.x, o2.y, o3.x, o3.y);
}

// ---------------- GEMM1 (tensor core, pre-split tf32, fused alpha) ------------
#define AS_STRIDE 20
#define AS_STAGE  (128 * AS_STRIDE)
#define BS_STRIDE 132
#define BS_STAGE  (16 * BS_STRIDE)
#define SMEM_F2   (2 * AS_STAGE + 2 * BS_STAGE)

__global__ __launch_bounds__(256) void k_gemm1_tc2(
        const float2* __restrict__ xsp, const float2* __restrict__ wsp,
        const float* __restrict__ a_src, const float* __restrict__ a_dst,
        __half* __restrict__ h1h, float* __restrict__ asrcn, float* __restrict__ adstn,
        int N) {
    extern __shared__ float2 smem[];
    const int t = threadIdx.x;
    const int warp = t >> 5, lane = t & 31;
    const int wm = warp >> 2, wn = warp & 3;
    const int lm = lane >> 2, lk = lane & 3;
    const int r0 = blockIdx.x * 128;
    const int n0 = blockIdx.y * 128;

    float acc[4][4][4];
#pragma unroll
    for (int i = 0; i < 4; i++)
#pragma unroll
        for (int j = 0; j < 4; j++)
#pragma unroll
            for (int v = 0; v < 4; v++) acc[i][j][v] = 0.f;

    auto issue = [&](int c, int buf) {
        int k0 = c * 16;
        float2* As = smem + buf * AS_STAGE;
        float2* Bs = smem + 2 * AS_STAGE + buf * BS_STAGE;
#pragma unroll
        for (int i = 0; i < 4; i++) {
            int op = t + i * 256;
            int row = op >> 3, seg = op & 7;
            int gr = r0 + row; if (gr > N - 1) gr = N - 1;
            cpasync16(As + row * AS_STRIDE + seg * 2,
                      xsp + (size_t)gr * 128 + k0 + seg * 2);
        }
#pragma unroll
        for (int i = 0; i < 4; i++) {
            int op = t + i * 256;
            int row = op >> 6, seg = op & 63;
            cpasync16(Bs + row * BS_STRIDE + seg * 2,
                      wsp + (size_t)(k0 + row) * 256 + n0 + seg * 2);
        }
        asm volatile("cp.async.commit_group;");
    };

    issue(0, 0);
    for (int c = 0; c < 8; c++) {
        int buf = c & 1;
        if (c < 7) {
            issue(c + 1, buf ^ 1);
            asm volatile("cp.async.wait_group 1;");
        } else {
            asm volatile("cp.async.wait_group 0;");
        }
        __syncthreads();
        const float2* As = smem + buf * AS_STAGE;
        const float2* Bs = smem + 2 * AS_STAGE + buf * BS_STAGE;
#pragma unroll
        for (int ks = 0; ks < 16; ks += 8) {
            unsigned Ah[4][4], Al[4][4];
#pragma unroll
            for (int mt = 0; mt < 4; mt++) {
                int mrow = wm * 64 + mt * 16 + lm;
                int c1 = ks + lk, c2 = c1 + 4;
                float2 p0 = As[mrow * AS_STRIDE + c1];
                float2 p1 = As[(mrow + 8) * AS_STRIDE + c1];
                float2 p2 = As[mrow * AS_STRIDE + c2];
                float2 p3 = As[(mrow + 8) * AS_STRIDE + c2];
                Ah[mt][0] = __float_as_uint(p0.x); Al[mt][0] = __float_as_uint(p0.y);
                Ah[mt][1] = __float_as_uint(p1.x); Al[mt][1] = __float_as_uint(p1.y);
                Ah[mt][2] = __float_as_uint(p2.x); Al[mt][2] = __float_as_uint(p2.y);
                Ah[mt][3] = __float_as_uint(p3.x); Al[mt][3] = __float_as_uint(p3.y);
            }
            unsigned Bh[4][2], Bl[4][2];
#pragma unroll
            for (int nt = 0; nt < 4; nt++) {
                int n = wn * 32 + nt * 8 + lm;
                float2 q0 = Bs[(ks + lk) * BS_STRIDE + n];
                float2 q1 = Bs[(ks + lk + 4) * BS_STRIDE + n];
                Bh[nt][0] = __float_as_uint(q0.x); Bl[nt][0] = __float_as_uint(q0.y);
                Bh[nt][1] = __float_as_uint(q1.x); Bl[nt][1] = __float_as_uint(q1.y);
            }
#pragma unroll
            for (int mt = 0; mt < 4; mt++)
#pragma unroll
                for (int nt = 0; nt < 4; nt++) {
                    mma_tf32(acc[mt][nt], Ah[mt], Bh[nt]);
                    mma_tf32(acc[mt][nt], Ah[mt], Bl[nt]);
                    mma_tf32(acc[mt][nt], Al[mt], Bh[nt]);
                }
        }
        __syncthreads();
    }

    const int h = blockIdx.y * 4 + wn;
    float2 asv[4], adv[4];
#pragma unroll
    for (int nt = 0; nt < 4; nt++) {
        asv[nt] = *reinterpret_cast<const float2*>(a_src + h * 32 + nt * 8 + lk * 2);
        adv[nt] = *reinterpret_cast<const float2*>(a_dst + h * 32 + nt * 8 + lk * 2);
    }
#pragma unroll
    for (int mt = 0; mt < 4; mt++) {
        int row1 = r0 + wm * 64 + mt * 16 + lm;
        int row2 = row1 + 8;
        float s1 = 0.f, d1 = 0.f, s2 = 0.f, d2 = 0.f;
#pragma unroll
        for (int nt = 0; nt < 4; nt++) {
            int col = n0 + wn * 32 + nt * 8 + lk * 2;
            s1 += acc[mt][nt][0] * asv[nt].x + acc[mt][nt][1] * asv[nt].y;
            d1 += acc[mt][nt][0] * adv[nt].x + acc[mt][nt][1] * adv[nt].y;
            s2 += acc[mt][nt][2] * asv[nt].x + acc[mt][nt][3] * asv[nt].y;
            d2 += acc[mt][nt][2] * adv[nt].x + acc[mt][nt][3] * adv[nt].y;
            if (row1 < N)
                *reinterpret_cast<__half2*>(h1h + (size_t)row1 * 256 + col) =
                    __floats2half2_rn(acc[mt][nt][0], acc[mt][nt][1]);
            if (row2 < N)
                *reinterpret_cast<__half2*>(h1h + (size_t)row2 * 256 + col) =
                    __floats2half2_rn(acc[mt][nt][2], acc[mt][nt][3]);
        }
        s1 += __shfl_xor_sync(0xffffffffu, s1, 1); s1 += __shfl_xor_sync(0xffffffffu, s1, 2);
        d1 += __shfl_xor_sync(0xffffffffu, d1, 1); d1 += __shfl_xor_sync(0xffffffffu, d1, 2);
        s2 += __shfl_xor_sync(0xffffffffu, s2, 1); s2 += __shfl_xor_sync(0xffffffffu, s2, 2);
        d2 += __shfl_xor_sync(0xffffffffu, d2, 1); d2 += __shfl_xor_sync(0xffffffffu, d2, 2);
        if (lk == 0) {
            if (row1 < N) { asrcn[row1 * 8 + h] = s1; adstn[row1 * 8 + h] = d1; }
            if (row2 < N) { asrcn[row2 * 8 + h] = s2; adstn[row2 * 8 + h] = d2; }
        }
    }
}

// ----- GAT1 pull aggregation + fused GEMM2 + alpha2 --------------------------
// warp per dst; after ELU, the warp holds the full 256-wide row in registers:
// compute h2 = row @ W2 (256x16) via per-lane partials + xor-tree reduction,
// then alpha2 projections. Deletes the separate gemm2 kernel and out1 buffer.
__global__ void k_agg1(const int* __restrict__ rowptr, const int* __restrict__ esrc,
                       const float* __restrict__ asrc, const float* __restrict__ adst,
                       const __half* __restrict__ h1h, const float* __restrict__ b1,
                       const float* __restrict__ W2, const float* __restrict__ a_src2,
                       const float* __restrict__ a_dst2,
                       __half* __restrict__ h2h, float* __restrict__ asrc2n,
                       float* __restrict__ adst2n, int N) {
    __shared__ float W2s[4096];
    for (int i = threadIdx.x; i < 4096; i += 256) W2s[i] = W2[i];
    __syncthreads();

    int d = (int)(((long long)blockIdx.x * blockDim.x + threadIdx.x) >> 5);
    int lane = threadIdx.x & 31;
    if (d >= N) return;
    int beg = rowptr[d], endp = rowptr[d + 1];
    float ad = (lane < 8) ? adst[d * 8 + lane] : 0.f;
    float den = 0.f;
    float accv[8];
#pragma unroll
    for (int i = 0; i < 8; i++) accv[i] = 0.f;
    const int h0 = lane >> 2;
    for (int base = beg; base < endp; base += 32) {
        int nn = min(32, endp - base);
        int sreg = (base + lane < endp) ? esrc[base + lane] : 0;
        int j = 0;
        for (; j + 1 < nn; j += 2) {
            int sA = __shfl_sync(0xffffffffu, sreg, j);
            int sB = __shfl_sync(0xffffffffu, sreg, j + 1);
            float wA = 0.f, wB = 0.f;
            if (lane < 8) {
                wA = __expf(lrelu(asrc[sA * 8 + lane] + ad));
                wB = __expf(lrelu(asrc[sB * 8 + lane] + ad));
            }
            den += wA + wB;
            float aA = __shfl_sync(0xffffffffu, wA, h0);
            float aB = __shfl_sync(0xffffffffu, wB, h0);
            uint4 rA = *reinterpret_cast<const uint4*>(h1h + (size_t)sA * 256 + lane * 8);
            uint4 rB = *reinterpret_cast<const uint4*>(h1h + (size_t)sB * 256 + lane * 8);
            float2 fA0 = __half22float2(*reinterpret_cast<__half2*>(&rA.x));
            float2 fA1 = __half22float2(*reinterpret_cast<__half2*>(&rA.y));
            float2 fA2 = __half22float2(*reinterpret_cast<__half2*>(&rA.z));
            float2 fA3 = __half22float2(*reinterpret_cast<__half2*>(&rA.w));
            float2 fB0 = __half22float2(*reinterpret_cast<__half2*>(&rB.x));
            float2 fB1 = __half22float2(*reinterpret_cast<__half2*>(&rB.y));
            float2 fB2 = __half22float2(*reinterpret_cast<__half2*>(&rB.z));
            float2 fB3 = __half22float2(*reinterpret_cast<__half2*>(&rB.w));
            accv[0] += fA0.x * aA + fB0.x * aB;
            accv[1] += fA0.y * aA + fB0.y * aB;
            accv[2] += fA1.x * aA + fB1.x * aB;
            accv[3] += fA1.y * aA + fB1.y * aB;
            accv[4] += fA2.x * aA + fB2.x * aB;
            accv[5] += fA2.y * aA + fB2.y * aB;
            accv[6] += fA3.x * aA + fB3.x * aB;
            accv[7] += fA3.y * aA + fB3.y * aB;
        }
        if (j < nn) {
            int s = __shfl_sync(0xffffffffu, sreg, j);
            float wgt = 0.f;
            if (lane < 8) wgt = __expf(lrelu(asrc[s * 8 + lane] + ad));
            den += wgt;
            float a = __shfl_sync(0xffffffffu, wgt, h0);
            uint4 r = *reinterpret_cast<const uint4*>(h1h + (size_t)s * 256 + lane * 8);
            float2 f0 = __half22float2(*reinterpret_cast<__half2*>(&r.x));
            float2 f1 = __half22float2(*reinterpret_cast<__half2*>(&r.y));
            float2 f2 = __half22float2(*reinterpret_cast<__half2*>(&r.z));
            float2 f3 = __half22float2(*reinterpret_cast<__half2*>(&r.w));
            accv[0] += f0.x * a; accv[1] += f0.y * a;
            accv[2] += f1.x * a; accv[3] += f1.y * a;
            accv[4] += f2.x * a; accv[5] += f2.y * a;
            accv[6] += f3.x * a; accv[7] += f3.y * a;
        }
    }
    float dn = __shfl_sync(0xffffffffu, den, h0);
    float rs = 1.f / dn;
    const float4* bp = reinterpret_cast<const float4*>(b1 + lane * 8);
    float4 bb0 = bp[0], bb1 = bp[1];
    float o[8];
    o[0] = eluf(accv[0] * rs + bb0.x); o[1] = eluf(accv[1] * rs + bb0.y);
    o[2] = eluf(accv[2] * rs + bb0.z); o[3] = eluf(accv[3] * rs + bb0.w);
    o[4] = eluf(accv[4] * rs + bb1.x); o[5] = eluf(accv[5] * rs + bb1.y);
    o[6] = eluf(accv[6] * rs + bb1.z); o[7] = eluf(accv[7] * rs + bb1.w);

    // ---- fused GEMM2: h2[c] = sum_k out1[k] * W2[k,c]; lane owns k=lane*8..+7
    float part[16];
#pragma unroll
    for (int c = 0; c < 16; c++) part[c] = 0.f;
    const float* w2row = W2s + lane * 8 * 16;
#pragma unroll
    for (int j = 0; j < 8; j++) {
        float oj = o[j];
        const float* wr = w2row + j * 16;
#pragma unroll
        for (int c = 0; c < 16; c++) part[c] += oj * wr[c];
    }
#pragma unroll
    for (int m = 16; m >= 1; m >>= 1) {
#pragma unroll
        for (int c = 0; c < 16; c++)
            part[c] += __shfl_xor_sync(0xffffffffu, part[c], m);
    }
    // every lane now holds the full h2 row
    if (lane < 4) {
        __half2 p0 = __floats2half2_rn(part[lane * 4 + 0], part[lane * 4 + 1]);
        __half2 p1 = __floats2half2_rn(part[lane * 4 + 2], part[lane * 4 + 3]);
        uint2 pk;
        pk.x = *reinterpret_cast<unsigned*>(&p0);
        pk.y = *reinterpret_cast<unsigned*>(&p1);
        *reinterpret_cast<uint2*>(h2h + (size_t)d * 16 + lane * 4) = pk;
    }
    float v1 = 0.f, v2 = 0.f;
    if (lane < 16) {
        v1 = part[lane] * a_src2[lane];
        v2 = part[lane] * a_dst2[lane];
    }
#pragma unroll
    for (int m = 8; m >= 1; m >>= 1) {
        v1 += __shfl_xor_sync(0xffffffffu, v1, m, 16);
        v2 += __shfl_xor_sync(0xffffffffu, v2, m, 16);
    }
    if (lane == 0) { asrc2n[d] = v1; adst2n[d] = v2; }
}

// ----- GAT2 pull aggregation + fused GCN transform (h3) ----------------------
__global__ void k_agg2(const int* __restrict__ rowptr, const int* __restrict__ esrc,
                       const float* __restrict__ asrc, const float* __restrict__ adst,
                       const __half* __restrict__ h2h, const float* __restrict__ b2,
                       const float* __restrict__ W3, __half* __restrict__ gh, int N) {
    __shared__ float W3s[256];
    if (threadIdx.x < 256) W3s[threadIdx.x] = W3[threadIdx.x];
    __syncthreads();
    long long gt = (long long)blockIdx.x * blockDim.x + threadIdx.x;
    int d = (int)(gt >> 2);
    int q = threadIdx.x & 3;
    if (d >= N) return;
    int beg = rowptr[d], endp = rowptr[d + 1];
    float ad = adst[d];
    float den = 0.f;
    float4 acc = {0, 0, 0, 0};
    for (int idx = beg; idx < endp; idx++) {
        int s = esrc[idx];
        float wgt = __expf(lrelu(asrc[s] + ad));
        den += wgt;
        uint2 r = *reinterpret_cast<const uint2*>(h2h + (size_t)s * 16 + q * 4);
        float2 f0 = __half22float2(*reinterpret_cast<__half2*>(&r.x));
        float2 f1 = __half22float2(*reinterpret_cast<__half2*>(&r.y));
        acc.x += f0.x * wgt; acc.y += f0.y * wgt;
        acc.z += f1.x * wgt; acc.w += f1.y * wgt;
    }
    float rr = 1.f / den;
    float4 bb = reinterpret_cast<const float4*>(b2)[q];
    float4 o;
    o.x = eluf(acc.x * rr + bb.x); o.y = eluf(acc.y * rr + bb.y);
    o.z = eluf(acc.z * rr + bb.z); o.w = eluf(acc.w * rr + bb.w);

    float v[16];
#pragma unroll
    for (int r = 0; r < 4; r++) {
        v[r * 4 + 0] = __shfl_sync(0xffffffffu, o.x, r, 4);
        v[r * 4 + 1] = __shfl_sync(0xffffffffu, o.y, r, 4);
        v[r * 4 + 2] = __shfl_sync(0xffffffffu, o.z, r, 4);
        v[r * 4 + 3] = __shfl_sync(0xffffffffu, o.w, r, 4);
    }
    float dv = rsqrtf((float)(endp - beg));
    float gacc[4];
#pragma unroll
    for (int j = 0; j < 4; j++) {
        int cc = q * 4 + j;
        float a = 0.f;
#pragma unroll
        for (int k = 0; k < 16; k++) a += v[k] * W3s[k * 16 + cc];
        gacc[j] = a * dv;
    }
    __half2 p0 = __floats2half2_rn(gacc[0], gacc[1]);
    __half2 p1 = __floats2half2_rn(gacc[2], gacc[3]);
    uint2 pk;
    pk.x = *reinterpret_cast<unsigned*>(&p0);
    pk.y = *reinterpret_cast<unsigned*>(&p1);
    *reinterpret_cast<uint2*>(gh + (size_t)d * 16 + q * 4) = pk;
}

// ----- GCN pull aggregation + finalize (fp16 gather) --------------------------
__global__ void k_agg3(const int* __restrict__ rowptr, const int* __restrict__ esrc,
                       const __half* __restrict__ gh, const float* __restrict__ b3,
                       float* __restrict__ out, int N) {
    long long gt = (long long)blockIdx.x * blockDim.x + threadIdx.x;
    int d = (int)(gt >> 2);
    int q = threadIdx.x & 3;
    if (d >= N) return;
    int beg = rowptr[d], endp = rowptr[d + 1];
    float4 acc = {0, 0, 0, 0};
    for (int idx = beg; idx < endp; idx++) {
        int s = esrc[idx];
        uint2 r = *reinterpret_cast<const uint2*>(gh + (size_t)s * 16 + q * 4);
        float2 f0 = __half22float2(*reinterpret_cast<__half2*>(&r.x));
        float2 f1 = __half22float2(*reinterpret_cast<__half2*>(&r.y));
        acc.x += f0.x; acc.y += f0.y; acc.z += f1.x; acc.w += f1.y;
    }
    float dv = rsqrtf((float)(endp - beg));
    float4 bb = reinterpret_cast<const float4*>(b3)[q];
    float4 o;
    o.x = acc.x * dv + bb.x; o.y = acc.y * dv + bb.y;
    o.z = acc.z * dv + bb.z; o.w = acc.w * dv + bb.w;
    reinterpret_cast<float4*>(out + (size_t)d * 16)[q] = o;
}

// ---------------------------------------------------------------------------
extern "C" void kernel_launch(void* const* d_in, const int* in_sizes, int n_in,
                              void* d_out, int out_size) {
    const float* x      = (const float*)d_in[0];
    const int*   ei     = (const int*)d_in[1];
    const float* W1     = (const float*)d_in[2];
    const float* a_src1 = (const float*)d_in[3];
    const float* a_dst1 = (const float*)d_in[4];
    const float* b1     = (const float*)d_in[5];
    const float* W2     = (const float*)d_in[6];
    const float* a_src2 = (const float*)d_in[7];
    const float* a_dst2 = (const float*)d_in[8];
    const float* b2     = (const float*)d_in[9];
    const float* W3     = (const float*)d_in[10];
    const float* b3     = (const float*)d_in[11];
    float* out = (float*)d_out;

    const int N = in_sizes[0] / 128;
    const int E = in_sizes[1] / 2;
    const int ET = E + N;

    float *asrc1, *adst1, *asrc2, *adst2;
    __half *h1h, *h2h, *gh;
    int *degi, *cursor, *rowptr, *esrc;
    float2 *xsp, *wsp;
    void* p;
    cudaGetSymbolAddress(&p, g_h1h);    h1h    = (__half*)p;
    cudaGetSymbolAddress(&p, g_asrc1);  asrc1  = (float*)p;
    cudaGetSymbolAddress(&p, g_adst1);  adst1  = (float*)p;
    cudaGetSymbolAddress(&p, g_h2h);    h2h    = (__half*)p;
    cudaGetSymbolAddress(&p, g_asrc2);  asrc2  = (float*)p;
    cudaGetSymbolAddress(&p, g_adst2);  adst2  = (float*)p;
    cudaGetSymbolAddress(&p, g_gh);     gh     = (__half*)p;
    cudaGetSymbolAddress(&p, g_degi);   degi   = (int*)p;
    cudaGetSymbolAddress(&p, g_cursor); cursor = (int*)p;
    cudaGetSymbolAddress(&p, g_rowptr); rowptr = (int*)p;
    cudaGetSymbolAddress(&p, g_esrc);   esrc   = (int*)p;
    cudaGetSymbolAddress(&p, g_xsp);    xsp    = (float2*)p;
    cudaGetSymbolAddress(&p, g_wsp);    wsp    = (float2*)p;

    static cudaStream_t s2 = nullptr;
    static cudaEvent_t evFork = nullptr, evJoin = nullptr, evW = nullptr;
    static int smem_set = 0;
    if (!s2) {
        cudaStreamCreateWithFlags(&s2, cudaStreamNonBlocking);
        cudaEventCreateWithFlags(&evFork, cudaEventDisableTiming);
        cudaEventCreateWithFlags(&evJoin, cudaEventDisableTiming);
        cudaEventCreateWithFlags(&evW, cudaEventDisableTiming);
    }
    if (!smem_set) {
        cudaFuncSetAttribute(k_gemm1_tc2,
                             cudaFuncAttributeMaxDynamicSharedMemorySize,
                             SMEM_F2 * (int)sizeof(float2));
        smem_set = 1;
    }

    const int B = 256;

    // ---- fork: W1 split + CSR chain on s2, concurrent with x split ----
    cudaEventRecord(evFork, 0);
    cudaStreamWaitEvent(s2, evFork, 0);

    k_split<<<(8192 + B - 1) / B, B, 0, s2>>>(W1, wsp, 8192);
    cudaEventRecord(evW, s2);
    cudaMemsetAsync(degi,   0, (size_t)N * sizeof(int), s2);
    cudaMemsetAsync(cursor, 0, (size_t)N * sizeof(int), s2);
    k_deg<<<(ET + B - 1) / B, B, 0, s2>>>(ei, E, N, degi);
    k_scan<<<1, 1024, 0, s2>>>(degi, rowptr, N, ET);
    k_fill<<<(ET + B - 1) / B, B, 0, s2>>>(ei, E, N, rowptr, cursor, esrc);
    cudaEventRecord(evJoin, s2);

    // main stream: x split, then tensor-core GEMM1 (needs wsp)
    k_split<<<(N * 32 + B - 1) / B, B>>>(x, xsp, N * 32);
    cudaStreamWaitEvent(0, evW, 0);
    {
        dim3 grid((N + 127) / 128, 2);
        k_gemm1_tc2<<<grid, 256, SMEM_F2 * sizeof(float2)>>>(
            xsp, wsp, a_src1, a_dst1, h1h, asrc1, adst1, N);
    }

    // ---- join: agg1 needs CSR ----
    cudaStreamWaitEvent(0, evJoin, 0);

    // Layer 1 aggregation + fused GEMM2 + alpha2
    {
        long long tot = (long long)N * 32;   // warp per dst
        k_agg1<<<(unsigned)((tot + B - 1) / B), B>>>(
            rowptr, esrc, asrc1, adst1, h1h, b1, W2, a_src2, a_dst2,
            h2h, asrc2, adst2, N);
    }

    // Layer 2 aggregation + fused GCN transform
    {
        long long tot = (long long)N * 4;
        k_agg2<<<(unsigned)((tot + B - 1) / B), B>>>(rowptr, esrc, asrc2, adst2, h2h, b2, W3, gh, N);
    }

    // Layer 3: GCN aggregation + finalize
    {
        long long tot = (long long)N * 4;
        k_agg3<<<(unsigned)((tot + B - 1) / B), B>>>(rowptr, esrc, gh, b3, out, N);
    }
}

// round 11
// speedup vs baseline: 2.2917x; 2.2917x over previous
#include <cuda_runtime.h>
#include <cuda_fp16.h>
#include <math.h>

#define NMAX 50000
#define EMAX 800000
#define ETMAX (EMAX + NMAX)

// ---------------- scratch (device globals) -----------------------------------
__device__ __half g_h1h[NMAX * 256];     // GAT1 features fp16 (gather payload)
__device__ float g_asrc1[NMAX * 8];
__device__ float g_adst1[NMAX * 8];
__device__ __half g_out1h[NMAX * 256];   // GAT1 output (post ELU), fp16
__device__ __half g_h2h[NMAX * 16];      // GAT2 features fp16
__device__ float g_asrc2[NMAX];
__device__ float g_adst2[NMAX];
__device__ __half g_gh[NMAX * 16];       // GCN per-src message fp16
__device__ int   g_degi[NMAX];
__device__ int   g_cursor[NMAX];
__device__ int   g_rowptr[NMAX + 1];
__device__ int   g_esrc[ETMAX];
__device__ float2 g_xsp[NMAX * 128];     // x split into (hi,lo) tf32 pairs
__device__ float2 g_wsp[128 * 256];      // W1 split

__device__ __forceinline__ float lrelu(float x) { return x > 0.f ? x : 0.2f * x; }
__device__ __forceinline__ float eluf(float x) { return x > 0.f ? x : expm1f(x); }

// ---------------- CSR build ---------------------------------------------------
__global__ void k_deg(const int* __restrict__ ei, int E, int N, int* __restrict__ degi) {
    int e = blockIdx.x * blockDim.x + threadIdx.x;
    int ET = E + N;
    if (e >= ET) return;
    int d = (e < E) ? ei[E + e] : e - E;
    atomicAdd(&degi[d], 1);
}

__global__ void k_scan(const int* __restrict__ degi, int* __restrict__ rowptr,
                       int N, int ET) {
    __shared__ int sh[1024];
    int t = threadIdx.x;
    int chunk = (N + 1023) / 1024;
    int start = t * chunk;
    int end = min(start + chunk, N);
    int sum = 0;
    for (int i = start; i < end; i++) sum += degi[i];
    sh[t] = sum;
    __syncthreads();
    for (int off = 1; off < 1024; off <<= 1) {
        int v = (t >= off) ? sh[t - off] : 0;
        __syncthreads();
        sh[t] += v;
        __syncthreads();
    }
    int run = (t == 0) ? 0 : sh[t - 1];
    for (int i = start; i < end; i++) { rowptr[i] = run; run += degi[i]; }
    if (t == 1023) rowptr[N] = ET;
}

__global__ void k_fill(const int* __restrict__ ei, int E, int N,
                       const int* __restrict__ rowptr, int* __restrict__ cursor,
                       int* __restrict__ esrc) {
    int e = blockIdx.x * blockDim.x + threadIdx.x;
    int ET = E + N;
    if (e >= ET) return;
    int s, d;
    if (e < E) { s = ei[e]; d = ei[E + e]; } else { s = d = e - E; }
    int pos = rowptr[d] + atomicAdd(&cursor[d], 1);
    esrc[pos] = s;
}

// ---------------- tf32 helpers ------------------------------------------------
__device__ __forceinline__ float2 tf32split2(float x) {
    unsigned u;
    asm("cvt.rna.tf32.f32 %0, %1;" : "=r"(u) : "f"(x));
    float hi = __uint_as_float(u);
    float r = x - hi;
    unsigned ul;
    asm("cvt.rna.tf32.f32 %0, %1;" : "=r"(ul) : "f"(r));
    return make_float2(hi, __uint_as_float(ul));
}

__device__ __forceinline__ void mma_tf32(float* d, const unsigned* a, const unsigned* b) {
    asm volatile("mma.sync.aligned.m16n8k8.row.col.f32.tf32.tf32.f32 "
                 "{%0,%1,%2,%3}, {%4,%5,%6,%7}, {%8,%9}, {%0,%1,%2,%3};"
                 : "+f"(d[0]), "+f"(d[1]), "+f"(d[2]), "+f"(d[3])
                 : "r"(a[0]), "r"(a[1]), "r"(a[2]), "r"(a[3]),
                   "r"(b[0]), "r"(b[1]));
}

__device__ __forceinline__ void cpasync16(void* dst, const void* src) {
    unsigned d = (unsigned)__cvta_generic_to_shared(dst);
    asm volatile("cp.async.cg.shared.global [%0], [%1], 16;" :: "r"(d), "l"(src));
}

// ---------------- split pass: f32 -> interleaved (hi,lo) ----------------------
__global__ void k_split(const float* __restrict__ src, float2* __restrict__ dst,
                        int total4) {
    int i = blockIdx.x * blockDim.x + threadIdx.x;
    if (i >= total4) return;
    float4 v = reinterpret_cast<const float4*>(src)[i];
    float2 o0 = tf32split2(v.x), o1 = tf32split2(v.y);
    float2 o2 = tf32split2(v.z), o3 = tf32split2(v.w);
    float4* d = reinterpret_cast<float4*>(dst + (size_t)i * 4);
    d[0] = make_float4(o0.x, o0.y, o1.x, o1.y);
    d[1] = make_float4(o2.x, o2.y, o3.x, o3.y);
}

// ---------------- GEMM1 (tensor core, pre-split tf32, fused alpha) ------------
#define AS_STRIDE 20
#define AS_STAGE  (128 * AS_STRIDE)
#define BS_STRIDE 132
#define BS_STAGE  (16 * BS_STRIDE)
#define SMEM_F2   (2 * AS_STAGE + 2 * BS_STAGE)

__global__ __launch_bounds__(256) void k_gemm1_tc2(
        const float2* __restrict__ xsp, const float2* __restrict__ wsp,
        const float* __restrict__ a_src, const float* __restrict__ a_dst,
        __half* __restrict__ h1h, float* __restrict__ asrcn, float* __restrict__ adstn,
        int N) {
    extern __shared__ float2 smem[];
    const int t = threadIdx.x;
    const int warp = t >> 5, lane = t & 31;
    const int wm = warp >> 2, wn = warp & 3;
    const int lm = lane >> 2, lk = lane & 3;
    const int r0 = blockIdx.x * 128;
    const int n0 = blockIdx.y * 128;

    float acc[4][4][4];
#pragma unroll
    for (int i = 0; i < 4; i++)
#pragma unroll
        for (int j = 0; j < 4; j++)
#pragma unroll
            for (int v = 0; v < 4; v++) acc[i][j][v] = 0.f;

    auto issue = [&](int c, int buf) {
        int k0 = c * 16;
        float2* As = smem + buf * AS_STAGE;
        float2* Bs = smem + 2 * AS_STAGE + buf * BS_STAGE;
#pragma unroll
        for (int i = 0; i < 4; i++) {
            int op = t + i * 256;
            int row = op >> 3, seg = op & 7;
            int gr = r0 + row; if (gr > N - 1) gr = N - 1;
            cpasync16(As + row * AS_STRIDE + seg * 2,
                      xsp + (size_t)gr * 128 + k0 + seg * 2);
        }
#pragma unroll
        for (int i = 0; i < 4; i++) {
            int op = t + i * 256;
            int row = op >> 6, seg = op & 63;
            cpasync16(Bs + row * BS_STRIDE + seg * 2,
                      wsp + (size_t)(k0 + row) * 256 + n0 + seg * 2);
        }
        asm volatile("cp.async.commit_group;");
    };

    issue(0, 0);
    for (int c = 0; c < 8; c++) {
        int buf = c & 1;
        if (c < 7) {
            issue(c + 1, buf ^ 1);
            asm volatile("cp.async.wait_group 1;");
        } else {
            asm volatile("cp.async.wait_group 0;");
        }
        __syncthreads();
        const float2* As = smem + buf * AS_STAGE;
        const float2* Bs = smem + 2 * AS_STAGE + buf * BS_STAGE;
#pragma unroll
        for (int ks = 0; ks < 16; ks += 8) {
            unsigned Ah[4][4], Al[4][4];
#pragma unroll
            for (int mt = 0; mt < 4; mt++) {
                int mrow = wm * 64 + mt * 16 + lm;
                int c1 = ks + lk, c2 = c1 + 4;
                float2 p0 = As[mrow * AS_STRIDE + c1];
                float2 p1 = As[(mrow + 8) * AS_STRIDE + c1];
                float2 p2 = As[mrow * AS_STRIDE + c2];
                float2 p3 = As[(mrow + 8) * AS_STRIDE + c2];
                Ah[mt][0] = __float_as_uint(p0.x); Al[mt][0] = __float_as_uint(p0.y);
                Ah[mt][1] = __float_as_uint(p1.x); Al[mt][1] = __float_as_uint(p1.y);
                Ah[mt][2] = __float_as_uint(p2.x); Al[mt][2] = __float_as_uint(p2.y);
                Ah[mt][3] = __float_as_uint(p3.x); Al[mt][3] = __float_as_uint(p3.y);
            }
            unsigned Bh[4][2], Bl[4][2];
#pragma unroll
            for (int nt = 0; nt < 4; nt++) {
                int n = wn * 32 + nt * 8 + lm;
                float2 q0 = Bs[(ks + lk) * BS_STRIDE + n];
                float2 q1 = Bs[(ks + lk + 4) * BS_STRIDE + n];
                Bh[nt][0] = __float_as_uint(q0.x); Bl[nt][0] = __float_as_uint(q0.y);
                Bh[nt][1] = __float_as_uint(q1.x); Bl[nt][1] = __float_as_uint(q1.y);
            }
#pragma unroll
            for (int mt = 0; mt < 4; mt++)
#pragma unroll
                for (int nt = 0; nt < 4; nt++) {
                    mma_tf32(acc[mt][nt], Ah[mt], Bh[nt]);
                    mma_tf32(acc[mt][nt], Ah[mt], Bl[nt]);
                    mma_tf32(acc[mt][nt], Al[mt], Bh[nt]);
                }
        }
        __syncthreads();
    }

    const int h = blockIdx.y * 4 + wn;
    float2 asv[4], adv[4];
#pragma unroll
    for (int nt = 0; nt < 4; nt++) {
        asv[nt] = *reinterpret_cast<const float2*>(a_src + h * 32 + nt * 8 + lk * 2);
        adv[nt] = *reinterpret_cast<const float2*>(a_dst + h * 32 + nt * 8 + lk * 2);
    }
#pragma unroll
    for (int mt = 0; mt < 4; mt++) {
        int row1 = r0 + wm * 64 + mt * 16 + lm;
        int row2 = row1 + 8;
        float s1 = 0.f, d1 = 0.f, s2 = 0.f, d2 = 0.f;
#pragma unroll
        for (int nt = 0; nt < 4; nt++) {
            int col = n0 + wn * 32 + nt * 8 + lk * 2;
            s1 += acc[mt][nt][0] * asv[nt].x + acc[mt][nt][1] * asv[nt].y;
            d1 += acc[mt][nt][0] * adv[nt].x + acc[mt][nt][1] * adv[nt].y;
            s2 += acc[mt][nt][2] * asv[nt].x + acc[mt][nt][3] * asv[nt].y;
            d2 += acc[mt][nt][2] * adv[nt].x + acc[mt][nt][3] * adv[nt].y;
            if (row1 < N)
                *reinterpret_cast<__half2*>(h1h + (size_t)row1 * 256 + col) =
                    __floats2half2_rn(acc[mt][nt][0], acc[mt][nt][1]);
            if (row2 < N)
                *reinterpret_cast<__half2*>(h1h + (size_t)row2 * 256 + col) =
                    __floats2half2_rn(acc[mt][nt][2], acc[mt][nt][3]);
        }
        s1 += __shfl_xor_sync(0xffffffffu, s1, 1); s1 += __shfl_xor_sync(0xffffffffu, s1, 2);
        d1 += __shfl_xor_sync(0xffffffffu, d1, 1); d1 += __shfl_xor_sync(0xffffffffu, d1, 2);
        s2 += __shfl_xor_sync(0xffffffffu, s2, 1); s2 += __shfl_xor_sync(0xffffffffu, s2, 2);
        d2 += __shfl_xor_sync(0xffffffffu, d2, 1); d2 += __shfl_xor_sync(0xffffffffu, d2, 2);
        if (lk == 0) {
            if (row1 < N) { asrcn[row1 * 8 + h] = s1; adstn[row1 * 8 + h] = d1; }
            if (row2 < N) { asrcn[row2 * 8 + h] = s2; adstn[row2 * 8 + h] = d2; }
        }
    }
}

// ----- GAT1 pull aggregation: warp per dst, fp16 in/out ----------------------
__global__ void k_agg1(const int* __restrict__ rowptr, const int* __restrict__ esrc,
                       const float* __restrict__ asrc, const float* __restrict__ adst,
                       const __half* __restrict__ h1h, const float* __restrict__ b1,
                       __half* __restrict__ out1h, int N) {
    int d = (int)(((long long)blockIdx.x * blockDim.x + threadIdx.x) >> 5);
    int lane = threadIdx.x & 31;
    if (d >= N) return;
    int beg = rowptr[d], endp = rowptr[d + 1];
    float ad = (lane < 8) ? adst[d * 8 + lane] : 0.f;
    float den = 0.f;
    float accv[8];
#pragma unroll
    for (int i = 0; i < 8; i++) accv[i] = 0.f;
    const int h0 = lane >> 2;
    for (int base = beg; base < endp; base += 32) {
        int nn = min(32, endp - base);
        int sreg = (base + lane < endp) ? esrc[base + lane] : 0;
        int j = 0;
        for (; j + 1 < nn; j += 2) {
            int sA = __shfl_sync(0xffffffffu, sreg, j);
            int sB = __shfl_sync(0xffffffffu, sreg, j + 1);
            float wA = 0.f, wB = 0.f;
            if (lane < 8) {
                wA = __expf(lrelu(asrc[sA * 8 + lane] + ad));
                wB = __expf(lrelu(asrc[sB * 8 + lane] + ad));
            }
            den += wA + wB;
            float aA = __shfl_sync(0xffffffffu, wA, h0);
            float aB = __shfl_sync(0xffffffffu, wB, h0);
            uint4 rA = *reinterpret_cast<const uint4*>(h1h + (size_t)sA * 256 + lane * 8);
            uint4 rB = *reinterpret_cast<const uint4*>(h1h + (size_t)sB * 256 + lane * 8);
            float2 fA0 = __half22float2(*reinterpret_cast<__half2*>(&rA.x));
            float2 fA1 = __half22float2(*reinterpret_cast<__half2*>(&rA.y));
            float2 fA2 = __half22float2(*reinterpret_cast<__half2*>(&rA.z));
            float2 fA3 = __half22float2(*reinterpret_cast<__half2*>(&rA.w));
            float2 fB0 = __half22float2(*reinterpret_cast<__half2*>(&rB.x));
            float2 fB1 = __half22float2(*reinterpret_cast<__half2*>(&rB.y));
            float2 fB2 = __half22float2(*reinterpret_cast<__half2*>(&rB.z));
            float2 fB3 = __half22float2(*reinterpret_cast<__half2*>(&rB.w));
            accv[0] += fA0.x * aA + fB0.x * aB;
            accv[1] += fA0.y * aA + fB0.y * aB;
            accv[2] += fA1.x * aA + fB1.x * aB;
            accv[3] += fA1.y * aA + fB1.y * aB;
            accv[4] += fA2.x * aA + fB2.x * aB;
            accv[5] += fA2.y * aA + fB2.y * aB;
            accv[6] += fA3.x * aA + fB3.x * aB;
            accv[7] += fA3.y * aA + fB3.y * aB;
        }
        if (j < nn) {
            int s = __shfl_sync(0xffffffffu, sreg, j);
            float wgt = 0.f;
            if (lane < 8) wgt = __expf(lrelu(asrc[s * 8 + lane] + ad));
            den += wgt;
            float a = __shfl_sync(0xffffffffu, wgt, h0);
            uint4 r = *reinterpret_cast<const uint4*>(h1h + (size_t)s * 256 + lane * 8);
            float2 f0 = __half22float2(*reinterpret_cast<__half2*>(&r.x));
            float2 f1 = __half22float2(*reinterpret_cast<__half2*>(&r.y));
            float2 f2 = __half22float2(*reinterpret_cast<__half2*>(&r.z));
            float2 f3 = __half22float2(*reinterpret_cast<__half2*>(&r.w));
            accv[0] += f0.x * a; accv[1] += f0.y * a;
            accv[2] += f1.x * a; accv[3] += f1.y * a;
            accv[4] += f2.x * a; accv[5] += f2.y * a;
            accv[6] += f3.x * a; accv[7] += f3.y * a;
        }
    }
    float dn = __shfl_sync(0xffffffffu, den, h0);
    float rs = 1.f / dn;
    const float4* bp = reinterpret_cast<const float4*>(b1 + lane * 8);
    float4 bb0 = bp[0], bb1 = bp[1];
    float o[8];
    o[0] = eluf(accv[0] * rs + bb0.x); o[1] = eluf(accv[1] * rs + bb0.y);
    o[2] = eluf(accv[2] * rs + bb0.z); o[3] = eluf(accv[3] * rs + bb0.w);
    o[4] = eluf(accv[4] * rs + bb1.x); o[5] = eluf(accv[5] * rs + bb1.y);
    o[6] = eluf(accv[6] * rs + bb1.z); o[7] = eluf(accv[7] * rs + bb1.w);
    __half2 p0 = __floats2half2_rn(o[0], o[1]);
    __half2 p1 = __floats2half2_rn(o[2], o[3]);
    __half2 p2 = __floats2half2_rn(o[4], o[5]);
    __half2 p3 = __floats2half2_rn(o[6], o[7]);
    uint4 pk;
    pk.x = *reinterpret_cast<unsigned*>(&p0);
    pk.y = *reinterpret_cast<unsigned*>(&p1);
    pk.z = *reinterpret_cast<unsigned*>(&p2);
    pk.w = *reinterpret_cast<unsigned*>(&p3);
    *reinterpret_cast<uint4*>(out1h + (size_t)d * 256 + lane * 8) = pk;
}

// ----- GEMM2: h2 = x2[N,256] @ W2[256,16], fp16 in (uint4), fused alpha2 -----
__global__ void k_gemm2(const __half* __restrict__ x2h, const float* __restrict__ W2,
                        const float* __restrict__ a_src2, const float* __restrict__ a_dst2,
                        __half* __restrict__ h2h, float* __restrict__ asrc2n,
                        float* __restrict__ adst2n, int N) {
    __shared__ float Wsh[256 * 16];
    int t = threadIdx.x;
    for (int i = t; i < 4096; i += 256) Wsh[i] = W2[i];
    __syncthreads();
    int n = blockIdx.x * 16 + (t >> 4);
    int c = t & 15;
    if (n >= N) return;
    float acc = 0.f;
    const uint4* xr4 = reinterpret_cast<const uint4*>(x2h + (size_t)n * 256);
#pragma unroll 8
    for (int kq = 0; kq < 32; kq++) {     // 32 uint4 x 8 halves = 256 K-terms
        uint4 r = xr4[kq];
        float2 f0 = __half22float2(*reinterpret_cast<__half2*>(&r.x));
        float2 f1 = __half22float2(*reinterpret_cast<__half2*>(&r.y));
        float2 f2 = __half22float2(*reinterpret_cast<__half2*>(&r.z));
        float2 f3 = __half22float2(*reinterpret_cast<__half2*>(&r.w));
        const float* wb = Wsh + (kq * 8) * 16 + c;
        acc += f0.x * wb[0]   + f0.y * wb[16]
             + f1.x * wb[32]  + f1.y * wb[48]
             + f2.x * wb[64]  + f2.y * wb[80]
             + f3.x * wb[96]  + f3.y * wb[112];
    }
    h2h[(size_t)n * 16 + c] = __float2half(acc);
    float r1 = acc * a_src2[c];
    float r2 = acc * a_dst2[c];
#pragma unroll
    for (int m = 8; m >= 1; m >>= 1) {
        r1 += __shfl_xor_sync(0xffffffffu, r1, m, 16);
        r2 += __shfl_xor_sync(0xffffffffu, r2, m, 16);
    }
    if (c == 0) { asrc2n[n] = r1; adst2n[n] = r2; }
}

// ----- GAT2 pull aggregation + fused GCN transform (h3) ----------------------
__global__ void k_agg2(const int* __restrict__ rowptr, const int* __restrict__ esrc,
                       const float* __restrict__ asrc, const float* __restrict__ adst,
                       const __half* __restrict__ h2h, const float* __restrict__ b2,
                       const float* __restrict__ W3, __half* __restrict__ gh, int N) {
    __shared__ float W3s[256];
    if (threadIdx.x < 256) W3s[threadIdx.x] = W3[threadIdx.x];
    __syncthreads();
    long long gt = (long long)blockIdx.x * blockDim.x + threadIdx.x;
    int d = (int)(gt >> 2);
    int q = threadIdx.x & 3;
    if (d >= N) return;
    int beg = rowptr[d], endp = rowptr[d + 1];
    float ad = adst[d];
    float den = 0.f;
    float4 acc = {0, 0, 0, 0};
    for (int idx = beg; idx < endp; idx++) {
        int s = esrc[idx];
        float wgt = __expf(lrelu(asrc[s] + ad));
        den += wgt;
        uint2 r = *reinterpret_cast<const uint2*>(h2h + (size_t)s * 16 + q * 4);
        float2 f0 = __half22float2(*reinterpret_cast<__half2*>(&r.x));
        float2 f1 = __half22float2(*reinterpret_cast<__half2*>(&r.y));
        acc.x += f0.x * wgt; acc.y += f0.y * wgt;
        acc.z += f1.x * wgt; acc.w += f1.y * wgt;
    }
    float rr = 1.f / den;
    float4 bb = reinterpret_cast<const float4*>(b2)[q];
    float4 o;
    o.x = eluf(acc.x * rr + bb.x); o.y = eluf(acc.y * rr + bb.y);
    o.z = eluf(acc.z * rr + bb.z); o.w = eluf(acc.w * rr + bb.w);

    // ---- fused h3: assemble full 16-vec across the 4-lane group ----
    float v[16];
#pragma unroll
    for (int r = 0; r < 4; r++) {
        v[r * 4 + 0] = __shfl_sync(0xffffffffu, o.x, r, 4);
        v[r * 4 + 1] = __shfl_sync(0xffffffffu, o.y, r, 4);
        v[r * 4 + 2] = __shfl_sync(0xffffffffu, o.z, r, 4);
        v[r * 4 + 3] = __shfl_sync(0xffffffffu, o.w, r, 4);
    }
    float dv = rsqrtf((float)(endp - beg));
    float gacc[4];
#pragma unroll
    for (int j = 0; j < 4; j++) {
        int cc = q * 4 + j;
        float a = 0.f;
#pragma unroll
        for (int k = 0; k < 16; k++) a += v[k] * W3s[k * 16 + cc];
        gacc[j] = a * dv;
    }
    __half2 p0 = __floats2half2_rn(gacc[0], gacc[1]);
    __half2 p1 = __floats2half2_rn(gacc[2], gacc[3]);
    uint2 pk;
    pk.x = *reinterpret_cast<unsigned*>(&p0);
    pk.y = *reinterpret_cast<unsigned*>(&p1);
    *reinterpret_cast<uint2*>(gh + (size_t)d * 16 + q * 4) = pk;
}

// ----- GCN pull aggregation + finalize (fp16 gather) --------------------------
__global__ void k_agg3(const int* __restrict__ rowptr, const int* __restrict__ esrc,
                       const __half* __restrict__ gh, const float* __restrict__ b3,
                       float* __restrict__ out, int N) {
    long long gt = (long long)blockIdx.x * blockDim.x + threadIdx.x;
    int d = (int)(gt >> 2);
    int q = threadIdx.x & 3;
    if (d >= N) return;
    int beg = rowptr[d], endp = rowptr[d + 1];
    float4 acc = {0, 0, 0, 0};
    for (int idx = beg; idx < endp; idx++) {
        int s = esrc[idx];
        uint2 r = *reinterpret_cast<const uint2*>(gh + (size_t)s * 16 + q * 4);
        float2 f0 = __half22float2(*reinterpret_cast<__half2*>(&r.x));
        float2 f1 = __half22float2(*reinterpret_cast<__half2*>(&r.y));
        acc.x += f0.x; acc.y += f0.y; acc.z += f1.x; acc.w += f1.y;
    }
    float dv = rsqrtf((float)(endp - beg));
    float4 bb = reinterpret_cast<const float4*>(b3)[q];
    float4 o;
    o.x = acc.x * dv + bb.x; o.y = acc.y * dv + bb.y;
    o.z = acc.z * dv + bb.z; o.w = acc.w * dv + bb.w;
    reinterpret_cast<float4*>(out + (size_t)d * 16)[q] = o;
}

// ---------------------------------------------------------------------------
extern "C" void kernel_launch(void* const* d_in, const int* in_sizes, int n_in,
                              void* d_out, int out_size) {
    const float* x      = (const float*)d_in[0];
    const int*   ei     = (const int*)d_in[1];
    const float* W1     = (const float*)d_in[2];
    const float* a_src1 = (const float*)d_in[3];
    const float* a_dst1 = (const float*)d_in[4];
    const float* b1     = (const float*)d_in[5];
    const float* W2     = (const float*)d_in[6];
    const float* a_src2 = (const float*)d_in[7];
    const float* a_dst2 = (const float*)d_in[8];
    const float* b2     = (const float*)d_in[9];
    const float* W3     = (const float*)d_in[10];
    const float* b3     = (const float*)d_in[11];
    float* out = (float*)d_out;

    const int N = in_sizes[0] / 128;
    const int E = in_sizes[1] / 2;
    const int ET = E + N;

    float *asrc1, *adst1, *asrc2, *adst2;
    __half *h1h, *out1h, *h2h, *gh;
    int *degi, *cursor, *rowptr, *esrc;
    float2 *xsp, *wsp;
    void* p;
    cudaGetSymbolAddress(&p, g_h1h);    h1h    = (__half*)p;
    cudaGetSymbolAddress(&p, g_asrc1);  asrc1  = (float*)p;
    cudaGetSymbolAddress(&p, g_adst1);  adst1  = (float*)p;
    cudaGetSymbolAddress(&p, g_out1h);  out1h  = (__half*)p;
    cudaGetSymbolAddress(&p, g_h2h);    h2h    = (__half*)p;
    cudaGetSymbolAddress(&p, g_asrc2);  asrc2  = (float*)p;
    cudaGetSymbolAddress(&p, g_adst2);  adst2  = (float*)p;
    cudaGetSymbolAddress(&p, g_gh);     gh     = (__half*)p;
    cudaGetSymbolAddress(&p, g_degi);   degi   = (int*)p;
    cudaGetSymbolAddress(&p, g_cursor); cursor = (int*)p;
    cudaGetSymbolAddress(&p, g_rowptr); rowptr = (int*)p;
    cudaGetSymbolAddress(&p, g_esrc);   esrc   = (int*)p;
    cudaGetSymbolAddress(&p, g_xsp);    xsp    = (float2*)p;
    cudaGetSymbolAddress(&p, g_wsp);    wsp    = (float2*)p;

    static cudaStream_t s2 = nullptr;
    static cudaEvent_t evFork = nullptr, evJoin = nullptr, evW = nullptr;
    static int smem_set = 0;
    if (!s2) {
        cudaStreamCreateWithFlags(&s2, cudaStreamNonBlocking);
        cudaEventCreateWithFlags(&evFork, cudaEventDisableTiming);
        cudaEventCreateWithFlags(&evJoin, cudaEventDisableTiming);
        cudaEventCreateWithFlags(&evW, cudaEventDisableTiming);
    }
    if (!smem_set) {
        cudaFuncSetAttribute(k_gemm1_tc2,
                             cudaFuncAttributeMaxDynamicSharedMemorySize,
                             SMEM_F2 * (int)sizeof(float2));
        smem_set = 1;
    }

    const int B = 256;

    // ---- fork: W1 split + CSR chain on s2, concurrent with x split ----
    cudaEventRecord(evFork, 0);
    cudaStreamWaitEvent(s2, evFork, 0);

    k_split<<<(8192 + B - 1) / B, B, 0, s2>>>(W1, wsp, 8192);
    cudaEventRecord(evW, s2);
    cudaMemsetAsync(degi,   0, (size_t)N * sizeof(int), s2);
    cudaMemsetAsync(cursor, 0, (size_t)N * sizeof(int), s2);
    k_deg<<<(ET + B - 1) / B, B, 0, s2>>>(ei, E, N, degi);
    k_scan<<<1, 1024, 0, s2>>>(degi, rowptr, N, ET);
    k_fill<<<(ET + B - 1) / B, B, 0, s2>>>(ei, E, N, rowptr, cursor, esrc);
    cudaEventRecord(evJoin, s2);

    // main stream: x split, then tensor-core GEMM1 (needs wsp)
    k_split<<<(N * 32 + B - 1) / B, B>>>(x, xsp, N * 32);
    cudaStreamWaitEvent(0, evW, 0);
    {
        dim3 grid((N + 127) / 128, 2);
        k_gemm1_tc2<<<grid, 256, SMEM_F2 * sizeof(float2)>>>(
            xsp, wsp, a_src1, a_dst1, h1h, asrc1, adst1, N);
    }

    // ---- join: agg1 needs CSR ----
    cudaStreamWaitEvent(0, evJoin, 0);

    {
        long long tot = (long long)N * 32;   // warp per dst
        k_agg1<<<(unsigned)((tot + B - 1) / B), B>>>(rowptr, esrc, asrc1, adst1, h1h, b1, out1h, N);
    }

    // Layer 2: GAT(256 -> 16, 1 head)
    k_gemm2<<<(N + 15) / 16, B>>>(out1h, W2, a_src2, a_dst2, h2h, asrc2, adst2, N);
    {
        long long tot = (long long)N * 4;
        k_agg2<<<(unsigned)((tot + B - 1) / B), B>>>(rowptr, esrc, asrc2, adst2, h2h, b2, W3, gh, N);
    }

    // Layer 3: GCN aggregation + finalize
    {
        long long tot = (long long)N * 4;
        k_agg3<<<(unsigned)((tot + B - 1) / B), B>>>(rowptr, esrc, gh, b3, out, N);
    }
}

// round 12
// speedup vs baseline: 2.5615x; 1.1177x over previous
#include <cuda_runtime.h>
#include <cuda_fp16.h>
#include <math.h>

#define NMAX 50000
#define EMAX 800000
#define ETMAX (EMAX + NMAX)

// ---------------- scratch (device globals) -----------------------------------
__device__ __half g_h1h[NMAX * 256];     // GAT1 features fp16 (gather payload)
__device__ float g_asrc1[NMAX * 8];
__device__ float g_adst1[NMAX * 8];
__device__ __half g_out1h[NMAX * 256];   // GAT1 output (post ELU), fp16
__device__ __half g_h2h[NMAX * 16];      // GAT2 features fp16
__device__ float g_asrc2[NMAX];
__device__ float g_adst2[NMAX];
__device__ __half g_gh[NMAX * 16];       // GCN per-src message fp16
__device__ int   g_degi[NMAX];
__device__ int   g_cursor[NMAX];
__device__ int   g_rowptr[NMAX + 1];
__device__ int   g_esrc[ETMAX];
__device__ __half g_xh[NMAX * 128];      // x fp16-split hi plane
__device__ __half g_xl[NMAX * 128];      // x fp16-split lo plane
__device__ __half g_wth[256 * 128];      // W1^T hi plane ([n][k])
__device__ __half g_wtl[256 * 128];      // W1^T lo plane

__device__ __forceinline__ float lrelu(float x) { return x > 0.f ? x : 0.2f * x; }
__device__ __forceinline__ float eluf(float x) { return x > 0.f ? x : expm1f(x); }

// ---------------- CSR build ---------------------------------------------------
__global__ void k_deg(const int* __restrict__ ei, int E, int N, int* __restrict__ degi) {
    int e = blockIdx.x * blockDim.x + threadIdx.x;
    int ET = E + N;
    if (e >= ET) return;
    int d = (e < E) ? ei[E + e] : e - E;
    atomicAdd(&degi[d], 1);
}

__global__ void k_scan(const int* __restrict__ degi, int* __restrict__ rowptr,
                       int N, int ET) {
    __shared__ int sh[1024];
    int t = threadIdx.x;
    int chunk = (N + 1023) / 1024;
    int start = t * chunk;
    int end = min(start + chunk, N);
    int sum = 0;
    for (int i = start; i < end; i++) sum += degi[i];
    sh[t] = sum;
    __syncthreads();
    for (int off = 1; off < 1024; off <<= 1) {
        int v = (t >= off) ? sh[t - off] : 0;
        __syncthreads();
        sh[t] += v;
        __syncthreads();
    }
    int run = (t == 0) ? 0 : sh[t - 1];
    for (int i = start; i < end; i++) { rowptr[i] = run; run += degi[i]; }
    if (t == 1023) rowptr[N] = ET;
}

__global__ void k_fill(const int* __restrict__ ei, int E, int N,
                       const int* __restrict__ rowptr, int* __restrict__ cursor,
                       int* __restrict__ esrc) {
    int e = blockIdx.x * blockDim.x + threadIdx.x;
    int ET = E + N;
    if (e >= ET) return;
    int s, d;
    if (e < E) { s = ei[e]; d = ei[E + e]; } else { s = d = e - E; }
    int pos = rowptr[d] + atomicAdd(&cursor[d], 1);
    esrc[pos] = s;
}

// ---------------- helpers ------------------------------------------------------
__device__ __forceinline__ void mma_f16(float* d, const unsigned* a, const unsigned* b) {
    asm volatile("mma.sync.aligned.m16n8k16.row.col.f32.f16.f16.f32 "
                 "{%0,%1,%2,%3}, {%4,%5,%6,%7}, {%8,%9}, {%0,%1,%2,%3};"
                 : "+f"(d[0]), "+f"(d[1]), "+f"(d[2]), "+f"(d[3])
                 : "r"(a[0]), "r"(a[1]), "r"(a[2]), "r"(a[3]),
                   "r"(b[0]), "r"(b[1]));
}

__device__ __forceinline__ void cpasync16(void* dst, const void* src) {
    unsigned d = (unsigned)__cvta_generic_to_shared(dst);
    asm volatile("cp.async.cg.shared.global [%0], [%1], 16;" :: "r"(d), "l"(src));
}

__device__ __forceinline__ void f16split(float x, __half& hi, __half& lo) {
    hi = __float2half_rn(x);
    lo = __float2half_rn(x - __half2float(hi));
}

// ---------------- split X: f32 -> hi/lo fp16 planes ---------------------------
__global__ void k_splitX(const float* __restrict__ src, __half* __restrict__ dh,
                         __half* __restrict__ dl, int total8) {
    int i = blockIdx.x * blockDim.x + threadIdx.x;   // each handles 8 elems
    if (i >= total8) return;
    const float4* s4 = reinterpret_cast<const float4*>(src) + (size_t)i * 2;
    float4 v0 = s4[0], v1 = s4[1];
    __half h[8], l[8];
    f16split(v0.x, h[0], l[0]); f16split(v0.y, h[1], l[1]);
    f16split(v0.z, h[2], l[2]); f16split(v0.w, h[3], l[3]);
    f16split(v1.x, h[4], l[4]); f16split(v1.y, h[5], l[5]);
    f16split(v1.z, h[6], l[6]); f16split(v1.w, h[7], l[7]);
    *reinterpret_cast<uint4*>(dh + (size_t)i * 8) = *reinterpret_cast<uint4*>(h);
    *reinterpret_cast<uint4*>(dl + (size_t)i * 8) = *reinterpret_cast<uint4*>(l);
}

// ---------------- split + transpose W1: [128][256] f32 -> [256][128] fp16 -----
__global__ void k_splitW(const float* __restrict__ W1, __half* __restrict__ dh,
                         __half* __restrict__ dl) {
    int i = blockIdx.x * blockDim.x + threadIdx.x;   // over 256*16
    if (i >= 256 * 16) return;
    int n = i >> 4, kq = i & 15;
    __half h[8], l[8];
#pragma unroll
    for (int j = 0; j < 8; j++)
        f16split(W1[(kq * 8 + j) * 256 + n], h[j], l[j]);
    *reinterpret_cast<uint4*>(dh + (size_t)n * 128 + kq * 8) = *reinterpret_cast<uint4*>(h);
    *reinterpret_cast<uint4*>(dl + (size_t)n * 128 + kq * 8) = *reinterpret_cast<uint4*>(l);
}

// ---------------- GEMM1 (fp16 2-term split, m16n8k16, fused alpha) ------------
// block tile 128m x 128n, 8 warps (2x4), warp tile 64x32, k-chunk 16, 2 stages
#define ASTR 24                       // smem stride in halves (conflict-free)
#define PL   (128 * ASTR)             // one plane (A or B), halves = 3072
#define STG  (4 * PL)                 // one stage: Ah, Al, Bh, Bl = 12288 halves
#define SMEM_H (2 * STG)              // two stages = 24576 halves = 48 KB

__global__ __launch_bounds__(256) void k_gemm1_tc3(
        const __half* __restrict__ xh, const __half* __restrict__ xl,
        const __half* __restrict__ wth, const __half* __restrict__ wtl,
        const float* __restrict__ a_src, const float* __restrict__ a_dst,
        __half* __restrict__ h1h, float* __restrict__ asrcn, float* __restrict__ adstn,
        int N) {
    extern __shared__ __half smh[];
    const int t = threadIdx.x;
    const int warp = t >> 5, lane = t & 31;
    const int wm = warp >> 2, wn = warp & 3;
    const int lm = lane >> 2, lk = lane & 3;
    const int r0 = blockIdx.x * 128;
    const int n0 = blockIdx.y * 128;

    float acc[4][4][4];
#pragma unroll
    for (int i = 0; i < 4; i++)
#pragma unroll
        for (int j = 0; j < 4; j++)
#pragma unroll
            for (int v = 0; v < 4; v++) acc[i][j][v] = 0.f;

    // chunk c covers k in [c*16, c*16+16). 4 planes x 256 x 16B each.
    auto issue = [&](int c, int buf) {
        int k0 = c * 16;
        __half* base = smh + buf * STG;
        int row = t >> 1, seg = t & 1;           // seg selects 8-half (16B) piece
        int gr = r0 + row; if (gr > N - 1) gr = N - 1;
        cpasync16(base + row * ASTR + seg * 8,
                  xh + (size_t)gr * 128 + k0 + seg * 8);
        cpasync16(base + PL + row * ASTR + seg * 8,
                  xl + (size_t)gr * 128 + k0 + seg * 8);
        cpasync16(base + 2 * PL + row * ASTR + seg * 8,
                  wth + (size_t)(n0 + row) * 128 + k0 + seg * 8);
        cpasync16(base + 3 * PL + row * ASTR + seg * 8,
                  wtl + (size_t)(n0 + row) * 128 + k0 + seg * 8);
        asm volatile("cp.async.commit_group;");
    };

    issue(0, 0);
    for (int c = 0; c < 8; c++) {
        int buf = c & 1;
        if (c < 7) {
            issue(c + 1, buf ^ 1);
            asm volatile("cp.async.wait_group 1;");
        } else {
            asm volatile("cp.async.wait_group 0;");
        }
        __syncthreads();
        const __half* Ah = smh + buf * STG;
        const __half* Al = Ah + PL;
        const __half* Bh = Ah + 2 * PL;
        const __half* Bl = Ah + 3 * PL;
        const int kb = lk * 2;

        unsigned Ahf[4][4], Alf[4][4];
#pragma unroll
        for (int mt = 0; mt < 4; mt++) {
            int mrow = wm * 64 + mt * 16 + lm;
            Ahf[mt][0] = *reinterpret_cast<const unsigned*>(Ah + mrow * ASTR + kb);
            Ahf[mt][1] = *reinterpret_cast<const unsigned*>(Ah + (mrow + 8) * ASTR + kb);
            Ahf[mt][2] = *reinterpret_cast<const unsigned*>(Ah + mrow * ASTR + kb + 8);
            Ahf[mt][3] = *reinterpret_cast<const unsigned*>(Ah + (mrow + 8) * ASTR + kb + 8);
            Alf[mt][0] = *reinterpret_cast<const unsigned*>(Al + mrow * ASTR + kb);
            Alf[mt][1] = *reinterpret_cast<const unsigned*>(Al + (mrow + 8) * ASTR + kb);
            Alf[mt][2] = *reinterpret_cast<const unsigned*>(Al + mrow * ASTR + kb + 8);
            Alf[mt][3] = *reinterpret_cast<const unsigned*>(Al + (mrow + 8) * ASTR + kb + 8);
        }
        unsigned Bhf[4][2], Blf[4][2];
#pragma unroll
        for (int nt = 0; nt < 4; nt++) {
            int n = wn * 32 + nt * 8 + lm;
            Bhf[nt][0] = *reinterpret_cast<const unsigned*>(Bh + n * ASTR + kb);
            Bhf[nt][1] = *reinterpret_cast<const unsigned*>(Bh + n * ASTR + kb + 8);
            Blf[nt][0] = *reinterpret_cast<const unsigned*>(Bl + n * ASTR + kb);
            Blf[nt][1] = *reinterpret_cast<const unsigned*>(Bl + n * ASTR + kb + 8);
        }
#pragma unroll
        for (int mt = 0; mt < 4; mt++)
#pragma unroll
            for (int nt = 0; nt < 4; nt++) {
                mma_f16(acc[mt][nt], Ahf[mt], Bhf[nt]);
                mma_f16(acc[mt][nt], Ahf[mt], Blf[nt]);
                mma_f16(acc[mt][nt], Alf[mt], Bhf[nt]);
            }
        __syncthreads();
    }

    // ---- epilogue: store h1 (fp16) + fused alpha projections ----
    const int h = blockIdx.y * 4 + wn;
    float2 asv[4], adv[4];
#pragma unroll
    for (int nt = 0; nt < 4; nt++) {
        asv[nt] = *reinterpret_cast<const float2*>(a_src + h * 32 + nt * 8 + lk * 2);
        adv[nt] = *reinterpret_cast<const float2*>(a_dst + h * 32 + nt * 8 + lk * 2);
    }
#pragma unroll
    for (int mt = 0; mt < 4; mt++) {
        int row1 = r0 + wm * 64 + mt * 16 + lm;
        int row2 = row1 + 8;
        float s1 = 0.f, d1 = 0.f, s2 = 0.f, d2 = 0.f;
#pragma unroll
        for (int nt = 0; nt < 4; nt++) {
            int col = n0 + wn * 32 + nt * 8 + lk * 2;
            s1 += acc[mt][nt][0] * asv[nt].x + acc[mt][nt][1] * asv[nt].y;
            d1 += acc[mt][nt][0] * adv[nt].x + acc[mt][nt][1] * adv[nt].y;
            s2 += acc[mt][nt][2] * asv[nt].x + acc[mt][nt][3] * asv[nt].y;
            d2 += acc[mt][nt][2] * adv[nt].x + acc[mt][nt][3] * adv[nt].y;
            if (row1 < N)
                *reinterpret_cast<__half2*>(h1h + (size_t)row1 * 256 + col) =
                    __floats2half2_rn(acc[mt][nt][0], acc[mt][nt][1]);
            if (row2 < N)
                *reinterpret_cast<__half2*>(h1h + (size_t)row2 * 256 + col) =
                    __floats2half2_rn(acc[mt][nt][2], acc[mt][nt][3]);
        }
        s1 += __shfl_xor_sync(0xffffffffu, s1, 1); s1 += __shfl_xor_sync(0xffffffffu, s1, 2);
        d1 += __shfl_xor_sync(0xffffffffu, d1, 1); d1 += __shfl_xor_sync(0xffffffffu, d1, 2);
        s2 += __shfl_xor_sync(0xffffffffu, s2, 1); s2 += __shfl_xor_sync(0xffffffffu, s2, 2);
        d2 += __shfl_xor_sync(0xffffffffu, d2, 1); d2 += __shfl_xor_sync(0xffffffffu, d2, 2);
        if (lk == 0) {
            if (row1 < N) { asrcn[row1 * 8 + h] = s1; adstn[row1 * 8 + h] = d1; }
            if (row2 < N) { asrcn[row2 * 8 + h] = s2; adstn[row2 * 8 + h] = d2; }
        }
    }
}

// ----- GAT1 pull aggregation: warp per dst, fp16 in/out ----------------------
__global__ void k_agg1(const int* __restrict__ rowptr, const int* __restrict__ esrc,
                       const float* __restrict__ asrc, const float* __restrict__ adst,
                       const __half* __restrict__ h1h, const float* __restrict__ b1,
                       __half* __restrict__ out1h, int N) {
    int d = (int)(((long long)blockIdx.x * blockDim.x + threadIdx.x) >> 5);
    int lane = threadIdx.x & 31;
    if (d >= N) return;
    int beg = rowptr[d], endp = rowptr[d + 1];
    float ad = (lane < 8) ? adst[d * 8 + lane] : 0.f;
    float den = 0.f;
    float accv[8];
#pragma unroll
    for (int i = 0; i < 8; i++) accv[i] = 0.f;
    const int h0 = lane >> 2;
    for (int base = beg; base < endp; base += 32) {
        int nn = min(32, endp - base);
        int sreg = (base + lane < endp) ? esrc[base + lane] : 0;
        int j = 0;
        for (; j + 1 < nn; j += 2) {
            int sA = __shfl_sync(0xffffffffu, sreg, j);
            int sB = __shfl_sync(0xffffffffu, sreg, j + 1);
            float wA = 0.f, wB = 0.f;
            if (lane < 8) {
                wA = __expf(lrelu(asrc[sA * 8 + lane] + ad));
                wB = __expf(lrelu(asrc[sB * 8 + lane] + ad));
            }
            den += wA + wB;
            float aA = __shfl_sync(0xffffffffu, wA, h0);
            float aB = __shfl_sync(0xffffffffu, wB, h0);
            uint4 rA = *reinterpret_cast<const uint4*>(h1h + (size_t)sA * 256 + lane * 8);
            uint4 rB = *reinterpret_cast<const uint4*>(h1h + (size_t)sB * 256 + lane * 8);
            float2 fA0 = __half22float2(*reinterpret_cast<__half2*>(&rA.x));
            float2 fA1 = __half22float2(*reinterpret_cast<__half2*>(&rA.y));
            float2 fA2 = __half22float2(*reinterpret_cast<__half2*>(&rA.z));
            float2 fA3 = __half22float2(*reinterpret_cast<__half2*>(&rA.w));
            float2 fB0 = __half22float2(*reinterpret_cast<__half2*>(&rB.x));
            float2 fB1 = __half22float2(*reinterpret_cast<__half2*>(&rB.y));
            float2 fB2 = __half22float2(*reinterpret_cast<__half2*>(&rB.z));
            float2 fB3 = __half22float2(*reinterpret_cast<__half2*>(&rB.w));
            accv[0] += fA0.x * aA + fB0.x * aB;
            accv[1] += fA0.y * aA + fB0.y * aB;
            accv[2] += fA1.x * aA + fB1.x * aB;
            accv[3] += fA1.y * aA + fB1.y * aB;
            accv[4] += fA2.x * aA + fB2.x * aB;
            accv[5] += fA2.y * aA + fB2.y * aB;
            accv[6] += fA3.x * aA + fB3.x * aB;
            accv[7] += fA3.y * aA + fB3.y * aB;
        }
        if (j < nn) {
            int s = __shfl_sync(0xffffffffu, sreg, j);
            float wgt = 0.f;
            if (lane < 8) wgt = __expf(lrelu(asrc[s * 8 + lane] + ad));
            den += wgt;
            float a = __shfl_sync(0xffffffffu, wgt, h0);
            uint4 r = *reinterpret_cast<const uint4*>(h1h + (size_t)s * 256 + lane * 8);
            float2 f0 = __half22float2(*reinterpret_cast<__half2*>(&r.x));
            float2 f1 = __half22float2(*reinterpret_cast<__half2*>(&r.y));
            float2 f2 = __half22float2(*reinterpret_cast<__half2*>(&r.z));
            float2 f3 = __half22float2(*reinterpret_cast<__half2*>(&r.w));
            accv[0] += f0.x * a; accv[1] += f0.y * a;
            accv[2] += f1.x * a; accv[3] += f1.y * a;
            accv[4] += f2.x * a; accv[5] += f2.y * a;
            accv[6] += f3.x * a; accv[7] += f3.y * a;
        }
    }
    float dn = __shfl_sync(0xffffffffu, den, h0);
    float rs = 1.f / dn;
    const float4* bp = reinterpret_cast<const float4*>(b1 + lane * 8);
    float4 bb0 = bp[0], bb1 = bp[1];
    float o[8];
    o[0] = eluf(accv[0] * rs + bb0.x); o[1] = eluf(accv[1] * rs + bb0.y);
    o[2] = eluf(accv[2] * rs + bb0.z); o[3] = eluf(accv[3] * rs + bb0.w);
    o[4] = eluf(accv[4] * rs + bb1.x); o[5] = eluf(accv[5] * rs + bb1.y);
    o[6] = eluf(accv[6] * rs + bb1.z); o[7] = eluf(accv[7] * rs + bb1.w);
    __half2 p0 = __floats2half2_rn(o[0], o[1]);
    __half2 p1 = __floats2half2_rn(o[2], o[3]);
    __half2 p2 = __floats2half2_rn(o[4], o[5]);
    __half2 p3 = __floats2half2_rn(o[6], o[7]);
    uint4 pk;
    pk.x = *reinterpret_cast<unsigned*>(&p0);
    pk.y = *reinterpret_cast<unsigned*>(&p1);
    pk.z = *reinterpret_cast<unsigned*>(&p2);
    pk.w = *reinterpret_cast<unsigned*>(&p3);
    *reinterpret_cast<uint4*>(out1h + (size_t)d * 256 + lane * 8) = pk;
}

// ----- GEMM2: h2 = x2[N,256] @ W2[256,16], fp16 in (uint4), fused alpha2 -----
__global__ void k_gemm2(const __half* __restrict__ x2h, const float* __restrict__ W2,
                        const float* __restrict__ a_src2, const float* __restrict__ a_dst2,
                        __half* __restrict__ h2h, float* __restrict__ asrc2n,
                        float* __restrict__ adst2n, int N) {
    __shared__ float Wsh[256 * 16];
    int t = threadIdx.x;
    for (int i = t; i < 4096; i += 256) Wsh[i] = W2[i];
    __syncthreads();
    int n = blockIdx.x * 16 + (t >> 4);
    int c = t & 15;
    if (n >= N) return;
    float acc = 0.f;
    const uint4* xr4 = reinterpret_cast<const uint4*>(x2h + (size_t)n * 256);
#pragma unroll 8
    for (int kq = 0; kq < 32; kq++) {     // 32 uint4 x 8 halves = 256 K-terms
        uint4 r = xr4[kq];
        float2 f0 = __half22float2(*reinterpret_cast<__half2*>(&r.x));
        float2 f1 = __half22float2(*reinterpret_cast<__half2*>(&r.y));
        float2 f2 = __half22float2(*reinterpret_cast<__half2*>(&r.z));
        float2 f3 = __half22float2(*reinterpret_cast<__half2*>(&r.w));
        const float* wb = Wsh + (kq * 8) * 16 + c;
        acc += f0.x * wb[0]   + f0.y * wb[16]
             + f1.x * wb[32]  + f1.y * wb[48]
             + f2.x * wb[64]  + f2.y * wb[80]
             + f3.x * wb[96]  + f3.y * wb[112];
    }
    h2h[(size_t)n * 16 + c] = __float2half(acc);
    float r1 = acc * a_src2[c];
    float r2 = acc * a_dst2[c];
#pragma unroll
    for (int m = 8; m >= 1; m >>= 1) {
        r1 += __shfl_xor_sync(0xffffffffu, r1, m, 16);
        r2 += __shfl_xor_sync(0xffffffffu, r2, m, 16);
    }
    if (c == 0) { asrc2n[n] = r1; adst2n[n] = r2; }
}

// ----- GAT2 pull aggregation + fused GCN transform (h3) ----------------------
__global__ void k_agg2(const int* __restrict__ rowptr, const int* __restrict__ esrc,
                       const float* __restrict__ asrc, const float* __restrict__ adst,
                       const __half* __restrict__ h2h, const float* __restrict__ b2,
                       const float* __restrict__ W3, __half* __restrict__ gh, int N) {
    __shared__ float W3s[256];
    if (threadIdx.x < 256) W3s[threadIdx.x] = W3[threadIdx.x];
    __syncthreads();
    long long gt = (long long)blockIdx.x * blockDim.x + threadIdx.x;
    int d = (int)(gt >> 2);
    int q = threadIdx.x & 3;
    if (d >= N) return;
    int beg = rowptr[d], endp = rowptr[d + 1];
    float ad = adst[d];
    float den = 0.f;
    float4 acc = {0, 0, 0, 0};
    for (int idx = beg; idx < endp; idx++) {
        int s = esrc[idx];
        float wgt = __expf(lrelu(asrc[s] + ad));
        den += wgt;
        uint2 r = *reinterpret_cast<const uint2*>(h2h + (size_t)s * 16 + q * 4);
        float2 f0 = __half22float2(*reinterpret_cast<__half2*>(&r.x));
        float2 f1 = __half22float2(*reinterpret_cast<__half2*>(&r.y));
        acc.x += f0.x * wgt; acc.y += f0.y * wgt;
        acc.z += f1.x * wgt; acc.w += f1.y * wgt;
    }
    float rr = 1.f / den;
    float4 bb = reinterpret_cast<const float4*>(b2)[q];
    float4 o;
    o.x = eluf(acc.x * rr + bb.x); o.y = eluf(acc.y * rr + bb.y);
    o.z = eluf(acc.z * rr + bb.z); o.w = eluf(acc.w * rr + bb.w);

    // ---- fused h3: assemble full 16-vec across the 4-lane group ----
    float v[16];
#pragma unroll
    for (int r = 0; r < 4; r++) {
        v[r * 4 + 0] = __shfl_sync(0xffffffffu, o.x, r, 4);
        v[r * 4 + 1] = __shfl_sync(0xffffffffu, o.y, r, 4);
        v[r * 4 + 2] = __shfl_sync(0xffffffffu, o.z, r, 4);
        v[r * 4 + 3] = __shfl_sync(0xffffffffu, o.w, r, 4);
    }
    float dv = rsqrtf((float)(endp - beg));
    float gacc[4];
#pragma unroll
    for (int j = 0; j < 4; j++) {
        int cc = q * 4 + j;
        float a = 0.f;
#pragma unroll
        for (int k = 0; k < 16; k++) a += v[k] * W3s[k * 16 + cc];
        gacc[j] = a * dv;
    }
    __half2 p0 = __floats2half2_rn(gacc[0], gacc[1]);
    __half2 p1 = __floats2half2_rn(gacc[2], gacc[3]);
    uint2 pk;
    pk.x = *reinterpret_cast<unsigned*>(&p0);
    pk.y = *reinterpret_cast<unsigned*>(&p1);
    *reinterpret_cast<uint2*>(gh + (size_t)d * 16 + q * 4) = pk;
}

// ----- GCN pull aggregation + finalize (fp16 gather) --------------------------
__global__ void k_agg3(const int* __restrict__ rowptr, const int* __restrict__ esrc,
                       const __half* __restrict__ gh, const float* __restrict__ b3,
                       float* __restrict__ out, int N) {
    long long gt = (long long)blockIdx.x * blockDim.x + threadIdx.x;
    int d = (int)(gt >> 2);
    int q = threadIdx.x & 3;
    if (d >= N) return;
    int beg = rowptr[d], endp = rowptr[d + 1];
    float4 acc = {0, 0, 0, 0};
    for (int idx = beg; idx < endp; idx++) {
        int s = esrc[idx];
        uint2 r = *reinterpret_cast<const uint2*>(gh + (size_t)s * 16 + q * 4);
        float2 f0 = __half22float2(*reinterpret_cast<__half2*>(&r.x));
        float2 f1 = __half22float2(*reinterpret_cast<__half2*>(&r.y));
        acc.x += f0.x; acc.y += f0.y; acc.z += f1.x; acc.w += f1.y;
    }
    float dv = rsqrtf((float)(endp - beg));
    float4 bb = reinterpret_cast<const float4*>(b3)[q];
    float4 o;
    o.x = acc.x * dv + bb.x; o.y = acc.y * dv + bb.y;
    o.z = acc.z * dv + bb.z; o.w = acc.w * dv + bb.w;
    reinterpret_cast<float4*>(out + (size_t)d * 16)[q] = o;
}

// ---------------------------------------------------------------------------
extern "C" void kernel_launch(void* const* d_in, const int* in_sizes, int n_in,
                              void* d_out, int out_size) {
    const float* x      = (const float*)d_in[0];
    const int*   ei     = (const int*)d_in[1];
    const float* W1     = (const float*)d_in[2];
    const float* a_src1 = (const float*)d_in[3];
    const float* a_dst1 = (const float*)d_in[4];
    const float* b1     = (const float*)d_in[5];
    const float* W2     = (const float*)d_in[6];
    const float* a_src2 = (const float*)d_in[7];
    const float* a_dst2 = (const float*)d_in[8];
    const float* b2     = (const float*)d_in[9];
    const float* W3     = (const float*)d_in[10];
    const float* b3     = (const float*)d_in[11];
    float* out = (float*)d_out;

    const int N = in_sizes[0] / 128;
    const int E = in_sizes[1] / 2;
    const int ET = E + N;

    float *asrc1, *adst1, *asrc2, *adst2;
    __half *h1h, *out1h, *h2h, *gh, *xh, *xl, *wth, *wtl;
    int *degi, *cursor, *rowptr, *esrc;
    void* p;
    cudaGetSymbolAddress(&p, g_h1h);    h1h    = (__half*)p;
    cudaGetSymbolAddress(&p, g_asrc1);  asrc1  = (float*)p;
    cudaGetSymbolAddress(&p, g_adst1);  adst1  = (float*)p;
    cudaGetSymbolAddress(&p, g_out1h);  out1h  = (__half*)p;
    cudaGetSymbolAddress(&p, g_h2h);    h2h    = (__half*)p;
    cudaGetSymbolAddress(&p, g_asrc2);  asrc2  = (float*)p;
    cudaGetSymbolAddress(&p, g_adst2);  adst2  = (float*)p;
    cudaGetSymbolAddress(&p, g_gh);     gh     = (__half*)p;
    cudaGetSymbolAddress(&p, g_degi);   degi   = (int*)p;
    cudaGetSymbolAddress(&p, g_cursor); cursor = (int*)p;
    cudaGetSymbolAddress(&p, g_rowptr); rowptr = (int*)p;
    cudaGetSymbolAddress(&p, g_esrc);   esrc   = (int*)p;
    cudaGetSymbolAddress(&p, g_xh);     xh     = (__half*)p;
    cudaGetSymbolAddress(&p, g_xl);     xl     = (__half*)p;
    cudaGetSymbolAddress(&p, g_wth);    wth    = (__half*)p;
    cudaGetSymbolAddress(&p, g_wtl);    wtl    = (__half*)p;

    static cudaStream_t s2 = nullptr;
    static cudaEvent_t evFork = nullptr, evJoin = nullptr, evW = nullptr;
    static int smem_set = 0;
    if (!s2) {
        cudaStreamCreateWithFlags(&s2, cudaStreamNonBlocking);
        cudaEventCreateWithFlags(&evFork, cudaEventDisableTiming);
        cudaEventCreateWithFlags(&evJoin, cudaEventDisableTiming);
        cudaEventCreateWithFlags(&evW, cudaEventDisableTiming);
    }
    if (!smem_set) {
        cudaFuncSetAttribute(k_gemm1_tc3,
                             cudaFuncAttributeMaxDynamicSharedMemorySize,
                             SMEM_H * (int)sizeof(__half));
        smem_set = 1;
    }

    const int B = 256;

    // ---- fork: W1 split + CSR chain on s2, concurrent with x split ----
    cudaEventRecord(evFork, 0);
    cudaStreamWaitEvent(s2, evFork, 0);

    k_splitW<<<(256 * 16 + B - 1) / B, B, 0, s2>>>(W1, wth, wtl);
    cudaEventRecord(evW, s2);
    cudaMemsetAsync(degi,   0, (size_t)N * sizeof(int), s2);
    cudaMemsetAsync(cursor, 0, (size_t)N * sizeof(int), s2);
    k_deg<<<(ET + B - 1) / B, B, 0, s2>>>(ei, E, N, degi);
    k_scan<<<1, 1024, 0, s2>>>(degi, rowptr, N, ET);
    k_fill<<<(ET + B - 1) / B, B, 0, s2>>>(ei, E, N, rowptr, cursor, esrc);
    cudaEventRecord(evJoin, s2);

    // main stream: x split, then fp16-split tensor-core GEMM1 (needs wth/wtl)
    k_splitX<<<(N * 16 + B - 1) / B, B>>>(x, xh, xl, N * 16);
    cudaStreamWaitEvent(0, evW, 0);
    {
        dim3 grid((N + 127) / 128, 2);
        k_gemm1_tc3<<<grid, 256, SMEM_H * sizeof(__half)>>>(
            xh, xl, wth, wtl, a_src1, a_dst1, h1h, asrc1, adst1, N);
    }

    // ---- join: agg1 needs CSR ----
    cudaStreamWaitEvent(0, evJoin, 0);

    {
        long long tot = (long long)N * 32;   // warp per dst
        k_agg1<<<(unsigned)((tot + B - 1) / B), B>>>(rowptr, esrc, asrc1, adst1, h1h, b1, out1h, N);
    }

    // Layer 2: GAT(256 -> 16, 1 head)
    k_gemm2<<<(N + 15) / 16, B>>>(out1h, W2, a_src2, a_dst2, h2h, asrc2, adst2, N);
    {
        long long tot = (long long)N * 4;
        k_agg2<<<(unsigned)((tot + B - 1) / B), B>>>(rowptr, esrc, asrc2, adst2, h2h, b2, W3, gh, N);
    }

    // Layer 3: GCN aggregation + finalize
    {
        long long tot = (long long)N * 4;
        k_agg3<<<(unsigned)((tot + B - 1) / B), B>>>(rowptr, esrc, gh, b3, out, N);
    }
}

// round 13
// speedup vs baseline: 2.5898x; 1.0110x over previous
#include <cuda_runtime.h>
#include <cuda_fp16.h>
#include <math.h>

#define NMAX 50000
#define EMAX 800000
#define ETMAX (EMAX + NMAX)

// ---------------- scratch (device globals) -----------------------------------
__device__ __half g_h1h[NMAX * 256];     // GAT1 features fp16 (gather payload)
__device__ float g_asrc1[NMAX * 8];
__device__ float g_adst1[NMAX * 8];
__device__ __half g_out1h[NMAX * 256];   // GAT1 output (post ELU), fp16
__device__ __half g_h2h[NMAX * 16];      // GAT2 features fp16
__device__ float g_asrc2[NMAX];
__device__ float g_adst2[NMAX];
__device__ __half g_gh[NMAX * 16];       // GCN per-src message fp16
__device__ int   g_degi[NMAX];
__device__ int   g_cursor[NMAX];
__device__ int   g_rowptr[NMAX + 1];
__device__ int   g_esrc[ETMAX];
__device__ __half g_xh[NMAX * 128];      // x fp16-split hi plane
__device__ __half g_xl[NMAX * 128];      // x fp16-split lo plane
__device__ __half g_wth[256 * 128];      // W1^T hi plane ([n][k])
__device__ __half g_wtl[256 * 128];      // W1^T lo plane

__device__ __forceinline__ float lrelu(float x) { return x > 0.f ? x : 0.2f * x; }
__device__ __forceinline__ float eluf(float x) { return x > 0.f ? x : expm1f(x); }

// ---------------- CSR build ---------------------------------------------------
__global__ void k_deg(const int* __restrict__ ei, int E, int N, int* __restrict__ degi) {
    int e = blockIdx.x * blockDim.x + threadIdx.x;
    int ET = E + N;
    if (e >= ET) return;
    int d = (e < E) ? ei[E + e] : e - E;
    atomicAdd(&degi[d], 1);
}

__global__ void k_scan(const int* __restrict__ degi, int* __restrict__ rowptr,
                       int N, int ET) {
    __shared__ int sh[1024];
    int t = threadIdx.x;
    int chunk = (N + 1023) / 1024;
    int start = t * chunk;
    int end = min(start + chunk, N);
    int sum = 0;
    for (int i = start; i < end; i++) sum += degi[i];
    sh[t] = sum;
    __syncthreads();
    for (int off = 1; off < 1024; off <<= 1) {
        int v = (t >= off) ? sh[t - off] : 0;
        __syncthreads();
        sh[t] += v;
        __syncthreads();
    }
    int run = (t == 0) ? 0 : sh[t - 1];
    for (int i = start; i < end; i++) { rowptr[i] = run; run += degi[i]; }
    if (t == 1023) rowptr[N] = ET;
}

__global__ void k_fill(const int* __restrict__ ei, int E, int N,
                       const int* __restrict__ rowptr, int* __restrict__ cursor,
                       int* __restrict__ esrc) {
    int e = blockIdx.x * blockDim.x + threadIdx.x;
    int ET = E + N;
    if (e >= ET) return;
    int s, d;
    if (e < E) { s = ei[e]; d = ei[E + e]; } else { s = d = e - E; }
    int pos = rowptr[d] + atomicAdd(&cursor[d], 1);
    esrc[pos] = s;
}

// ---------------- helpers ------------------------------------------------------
__device__ __forceinline__ void mma_f16(float* d, const unsigned* a, const unsigned* b) {
    asm volatile("mma.sync.aligned.m16n8k16.row.col.f32.f16.f16.f32 "
                 "{%0,%1,%2,%3}, {%4,%5,%6,%7}, {%8,%9}, {%0,%1,%2,%3};"
                 : "+f"(d[0]), "+f"(d[1]), "+f"(d[2]), "+f"(d[3])
                 : "r"(a[0]), "r"(a[1]), "r"(a[2]), "r"(a[3]),
                   "r"(b[0]), "r"(b[1]));
}

__device__ __forceinline__ void cpasync16(void* dst, const void* src) {
    unsigned d = (unsigned)__cvta_generic_to_shared(dst);
    asm volatile("cp.async.cg.shared.global [%0], [%1], 16;" :: "r"(d), "l"(src));
}

__device__ __forceinline__ void f16split(float x, __half& hi, __half& lo) {
    hi = __float2half_rn(x);
    lo = __float2half_rn(x - __half2float(hi));
}

// ---------------- split X: f32 -> hi/lo fp16 planes ---------------------------
__global__ void k_splitX(const float* __restrict__ src, __half* __restrict__ dh,
                         __half* __restrict__ dl, int total8) {
    int i = blockIdx.x * blockDim.x + threadIdx.x;   // each handles 8 elems
    if (i >= total8) return;
    const float4* s4 = reinterpret_cast<const float4*>(src) + (size_t)i * 2;
    float4 v0 = s4[0], v1 = s4[1];
    __half h[8], l[8];
    f16split(v0.x, h[0], l[0]); f16split(v0.y, h[1], l[1]);
    f16split(v0.z, h[2], l[2]); f16split(v0.w, h[3], l[3]);
    f16split(v1.x, h[4], l[4]); f16split(v1.y, h[5], l[5]);
    f16split(v1.z, h[6], l[6]); f16split(v1.w, h[7], l[7]);
    *reinterpret_cast<uint4*>(dh + (size_t)i * 8) = *reinterpret_cast<uint4*>(h);
    *reinterpret_cast<uint4*>(dl + (size_t)i * 8) = *reinterpret_cast<uint4*>(l);
}

// ---------------- split + transpose W1: [128][256] f32 -> [256][128] fp16 -----
__global__ void k_splitW(const float* __restrict__ W1, __half* __restrict__ dh,
                         __half* __restrict__ dl) {
    int i = blockIdx.x * blockDim.x + threadIdx.x;   // over 256*16
    if (i >= 256 * 16) return;
    int n = i >> 4, kq = i & 15;
    __half h[8], l[8];
#pragma unroll
    for (int j = 0; j < 8; j++)
        f16split(W1[(kq * 8 + j) * 256 + n], h[j], l[j]);
    *reinterpret_cast<uint4*>(dh + (size_t)n * 128 + kq * 8) = *reinterpret_cast<uint4*>(h);
    *reinterpret_cast<uint4*>(dl + (size_t)n * 128 + kq * 8) = *reinterpret_cast<uint4*>(l);
}

// ---------------- GEMM1 (fp16 2-term split, m16n8k16, fused alpha) ------------
#define ASTR 24
#define PL   (128 * ASTR)
#define STG  (4 * PL)
#define SMEM_H (2 * STG)

__global__ __launch_bounds__(256) void k_gemm1_tc3(
        const __half* __restrict__ xh, const __half* __restrict__ xl,
        const __half* __restrict__ wth, const __half* __restrict__ wtl,
        const float* __restrict__ a_src, const float* __restrict__ a_dst,
        __half* __restrict__ h1h, float* __restrict__ asrcn, float* __restrict__ adstn,
        int N) {
    extern __shared__ __half smh[];
    const int t = threadIdx.x;
    const int warp = t >> 5, lane = t & 31;
    const int wm = warp >> 2, wn = warp & 3;
    const int lm = lane >> 2, lk = lane & 3;
    const int r0 = blockIdx.x * 128;
    const int n0 = blockIdx.y * 128;

    float acc[4][4][4];
#pragma unroll
    for (int i = 0; i < 4; i++)
#pragma unroll
        for (int j = 0; j < 4; j++)
#pragma unroll
            for (int v = 0; v < 4; v++) acc[i][j][v] = 0.f;

    auto issue = [&](int c, int buf) {
        int k0 = c * 16;
        __half* base = smh + buf * STG;
        int row = t >> 1, seg = t & 1;
        int gr = r0 + row; if (gr > N - 1) gr = N - 1;
        cpasync16(base + row * ASTR + seg * 8,
                  xh + (size_t)gr * 128 + k0 + seg * 8);
        cpasync16(base + PL + row * ASTR + seg * 8,
                  xl + (size_t)gr * 128 + k0 + seg * 8);
        cpasync16(base + 2 * PL + row * ASTR + seg * 8,
                  wth + (size_t)(n0 + row) * 128 + k0 + seg * 8);
        cpasync16(base + 3 * PL + row * ASTR + seg * 8,
                  wtl + (size_t)(n0 + row) * 128 + k0 + seg * 8);
        asm volatile("cp.async.commit_group;");
    };

    issue(0, 0);
    for (int c = 0; c < 8; c++) {
        int buf = c & 1;
        if (c < 7) {
            issue(c + 1, buf ^ 1);
            asm volatile("cp.async.wait_group 1;");
        } else {
            asm volatile("cp.async.wait_group 0;");
        }
        __syncthreads();
        const __half* Ah = smh + buf * STG;
        const __half* Al = Ah + PL;
        const __half* Bh = Ah + 2 * PL;
        const __half* Bl = Ah + 3 * PL;
        const int kb = lk * 2;

        unsigned Ahf[4][4], Alf[4][4];
#pragma unroll
        for (int mt = 0; mt < 4; mt++) {
            int mrow = wm * 64 + mt * 16 + lm;
            Ahf[mt][0] = *reinterpret_cast<const unsigned*>(Ah + mrow * ASTR + kb);
            Ahf[mt][1] = *reinterpret_cast<const unsigned*>(Ah + (mrow + 8) * ASTR + kb);
            Ahf[mt][2] = *reinterpret_cast<const unsigned*>(Ah + mrow * ASTR + kb + 8);
            Ahf[mt][3] = *reinterpret_cast<const unsigned*>(Ah + (mrow + 8) * ASTR + kb + 8);
            Alf[mt][0] = *reinterpret_cast<const unsigned*>(Al + mrow * ASTR + kb);
            Alf[mt][1] = *reinterpret_cast<const unsigned*>(Al + (mrow + 8) * ASTR + kb);
            Alf[mt][2] = *reinterpret_cast<const unsigned*>(Al + mrow * ASTR + kb + 8);
            Alf[mt][3] = *reinterpret_cast<const unsigned*>(Al + (mrow + 8) * ASTR + kb + 8);
        }
        unsigned Bhf[4][2], Blf[4][2];
#pragma unroll
        for (int nt = 0; nt < 4; nt++) {
            int n = wn * 32 + nt * 8 + lm;
            Bhf[nt][0] = *reinterpret_cast<const unsigned*>(Bh + n * ASTR + kb);
            Bhf[nt][1] = *reinterpret_cast<const unsigned*>(Bh + n * ASTR + kb + 8);
            Blf[nt][0] = *reinterpret_cast<const unsigned*>(Bl + n * ASTR + kb);
            Blf[nt][1] = *reinterpret_cast<const unsigned*>(Bl + n * ASTR + kb + 8);
        }
#pragma unroll
        for (int mt = 0; mt < 4; mt++)
#pragma unroll
            for (int nt = 0; nt < 4; nt++) {
                mma_f16(acc[mt][nt], Ahf[mt], Bhf[nt]);
                mma_f16(acc[mt][nt], Ahf[mt], Blf[nt]);
                mma_f16(acc[mt][nt], Alf[mt], Bhf[nt]);
            }
        __syncthreads();
    }

    // ---- epilogue: store h1 (fp16) + fused alpha projections ----
    const int h = blockIdx.y * 4 + wn;
    float2 asv[4], adv[4];
#pragma unroll
    for (int nt = 0; nt < 4; nt++) {
        asv[nt] = *reinterpret_cast<const float2*>(a_src + h * 32 + nt * 8 + lk * 2);
        adv[nt] = *reinterpret_cast<const float2*>(a_dst + h * 32 + nt * 8 + lk * 2);
    }
#pragma unroll
    for (int mt = 0; mt < 4; mt++) {
        int row1 = r0 + wm * 64 + mt * 16 + lm;
        int row2 = row1 + 8;
        float s1 = 0.f, d1 = 0.f, s2 = 0.f, d2 = 0.f;
#pragma unroll
        for (int nt = 0; nt < 4; nt++) {
            int col = n0 + wn * 32 + nt * 8 + lk * 2;
            s1 += acc[mt][nt][0] * asv[nt].x + acc[mt][nt][1] * asv[nt].y;
            d1 += acc[mt][nt][0] * adv[nt].x + acc[mt][nt][1] * adv[nt].y;
            s2 += acc[mt][nt][2] * asv[nt].x + acc[mt][nt][3] * asv[nt].y;
            d2 += acc[mt][nt][2] * adv[nt].x + acc[mt][nt][3] * adv[nt].y;
            if (row1 < N)
                *reinterpret_cast<__half2*>(h1h + (size_t)row1 * 256 + col) =
                    __floats2half2_rn(acc[mt][nt][0], acc[mt][nt][1]);
            if (row2 < N)
                *reinterpret_cast<__half2*>(h1h + (size_t)row2 * 256 + col) =
                    __floats2half2_rn(acc[mt][nt][2], acc[mt][nt][3]);
        }
        s1 += __shfl_xor_sync(0xffffffffu, s1, 1); s1 += __shfl_xor_sync(0xffffffffu, s1, 2);
        d1 += __shfl_xor_sync(0xffffffffu, d1, 1); d1 += __shfl_xor_sync(0xffffffffu, d1, 2);
        s2 += __shfl_xor_sync(0xffffffffu, s2, 1); s2 += __shfl_xor_sync(0xffffffffu, s2, 2);
        d2 += __shfl_xor_sync(0xffffffffu, d2, 1); d2 += __shfl_xor_sync(0xffffffffu, d2, 2);
        if (lk == 0) {
            if (row1 < N) { asrcn[row1 * 8 + h] = s1; adstn[row1 * 8 + h] = d1; }
            if (row2 < N) { asrcn[row2 * 8 + h] = s2; adstn[row2 * 8 + h] = d2; }
        }
    }
}

// ----- GAT1 pull aggregation: warp per dst, direct per-lane head weights -----
__global__ void k_agg1(const int* __restrict__ rowptr, const int* __restrict__ esrc,
                       const float* __restrict__ asrc, const float* __restrict__ adst,
                       const __half* __restrict__ h1h, const float* __restrict__ b1,
                       __half* __restrict__ out1h, int N) {
    int d = (int)(((long long)blockIdx.x * blockDim.x + threadIdx.x) >> 5);
    int lane = threadIdx.x & 31;
    if (d >= N) return;
    int beg = rowptr[d], endp = rowptr[d + 1];
    const int h0 = lane >> 2;                 // head owning this lane's 8 cols
    float ad = adst[d * 8 + h0];              // broadcast within 4-lane group
    float den = 0.f;
    float accv[8];
#pragma unroll
    for (int i = 0; i < 8; i++) accv[i] = 0.f;
    for (int base = beg; base < endp; base += 32) {
        int nn = min(32, endp - base);
        int sreg = (base + lane < endp) ? esrc[base + lane] : 0;
        int j = 0;
        for (; j + 1 < nn; j += 2) {
            int sA = __shfl_sync(0xffffffffu, sreg, j);
            int sB = __shfl_sync(0xffffffffu, sreg, j + 1);
            float aA = __expf(lrelu(asrc[sA * 8 + h0] + ad));
            float aB = __expf(lrelu(asrc[sB * 8 + h0] + ad));
            den += aA + aB;
            uint4 rA = *reinterpret_cast<const uint4*>(h1h + (size_t)sA * 256 + lane * 8);
            uint4 rB = *reinterpret_cast<const uint4*>(h1h + (size_t)sB * 256 + lane * 8);
            float2 fA0 = __half22float2(*reinterpret_cast<__half2*>(&rA.x));
            float2 fA1 = __half22float2(*reinterpret_cast<__half2*>(&rA.y));
            float2 fA2 = __half22float2(*reinterpret_cast<__half2*>(&rA.z));
            float2 fA3 = __half22float2(*reinterpret_cast<__half2*>(&rA.w));
            float2 fB0 = __half22float2(*reinterpret_cast<__half2*>(&rB.x));
            float2 fB1 = __half22float2(*reinterpret_cast<__half2*>(&rB.y));
            float2 fB2 = __half22float2(*reinterpret_cast<__half2*>(&rB.z));
            float2 fB3 = __half22float2(*reinterpret_cast<__half2*>(&rB.w));
            accv[0] += fA0.x * aA + fB0.x * aB;
            accv[1] += fA0.y * aA + fB0.y * aB;
            accv[2] += fA1.x * aA + fB1.x * aB;
            accv[3] += fA1.y * aA + fB1.y * aB;
            accv[4] += fA2.x * aA + fB2.x * aB;
            accv[5] += fA2.y * aA + fB2.y * aB;
            accv[6] += fA3.x * aA + fB3.x * aB;
            accv[7] += fA3.y * aA + fB3.y * aB;
        }
        if (j < nn) {
            int s = __shfl_sync(0xffffffffu, sreg, j);
            float a = __expf(lrelu(asrc[s * 8 + h0] + ad));
            den += a;
            uint4 r = *reinterpret_cast<const uint4*>(h1h + (size_t)s * 256 + lane * 8);
            float2 f0 = __half22float2(*reinterpret_cast<__half2*>(&r.x));
            float2 f1 = __half22float2(*reinterpret_cast<__half2*>(&r.y));
            float2 f2 = __half22float2(*reinterpret_cast<__half2*>(&r.z));
            float2 f3 = __half22float2(*reinterpret_cast<__half2*>(&r.w));
            accv[0] += f0.x * a; accv[1] += f0.y * a;
            accv[2] += f1.x * a; accv[3] += f1.y * a;
            accv[4] += f2.x * a; accv[5] += f2.y * a;
            accv[6] += f3.x * a; accv[7] += f3.y * a;
        }
    }
    float rs = 1.f / den;                     // den identical within 4-lane group
    const float4* bp = reinterpret_cast<const float4*>(b1 + lane * 8);
    float4 bb0 = bp[0], bb1 = bp[1];
    float o[8];
    o[0] = eluf(accv[0] * rs + bb0.x); o[1] = eluf(accv[1] * rs + bb0.y);
    o[2] = eluf(accv[2] * rs + bb0.z); o[3] = eluf(accv[3] * rs + bb0.w);
    o[4] = eluf(accv[4] * rs + bb1.x); o[5] = eluf(accv[5] * rs + bb1.y);
    o[6] = eluf(accv[6] * rs + bb1.z); o[7] = eluf(accv[7] * rs + bb1.w);
    __half2 p0 = __floats2half2_rn(o[0], o[1]);
    __half2 p1 = __floats2half2_rn(o[2], o[3]);
    __half2 p2 = __floats2half2_rn(o[4], o[5]);
    __half2 p3 = __floats2half2_rn(o[6], o[7]);
    uint4 pk;
    pk.x = *reinterpret_cast<unsigned*>(&p0);
    pk.y = *reinterpret_cast<unsigned*>(&p1);
    pk.z = *reinterpret_cast<unsigned*>(&p2);
    pk.w = *reinterpret_cast<unsigned*>(&p3);
    *reinterpret_cast<uint4*>(out1h + (size_t)d * 256 + lane * 8) = pk;
}

// ----- GEMM2: h2 = x2[N,256] @ W2[256,16], fp16 in (uint4), fused alpha2 -----
__global__ void k_gemm2(const __half* __restrict__ x2h, const float* __restrict__ W2,
                        const float* __restrict__ a_src2, const float* __restrict__ a_dst2,
                        __half* __restrict__ h2h, float* __restrict__ asrc2n,
                        float* __restrict__ adst2n, int N) {
    __shared__ float Wsh[256 * 16];
    int t = threadIdx.x;
    for (int i = t; i < 4096; i += 256) Wsh[i] = W2[i];
    __syncthreads();
    int n = blockIdx.x * 16 + (t >> 4);
    int c = t & 15;
    if (n >= N) return;
    float acc = 0.f;
    const uint4* xr4 = reinterpret_cast<const uint4*>(x2h + (size_t)n * 256);
#pragma unroll 8
    for (int kq = 0; kq < 32; kq++) {
        uint4 r = xr4[kq];
        float2 f0 = __half22float2(*reinterpret_cast<__half2*>(&r.x));
        float2 f1 = __half22float2(*reinterpret_cast<__half2*>(&r.y));
        float2 f2 = __half22float2(*reinterpret_cast<__half2*>(&r.z));
        float2 f3 = __half22float2(*reinterpret_cast<__half2*>(&r.w));
        const float* wb = Wsh + (kq * 8) * 16 + c;
        acc += f0.x * wb[0]   + f0.y * wb[16]
             + f1.x * wb[32]  + f1.y * wb[48]
             + f2.x * wb[64]  + f2.y * wb[80]
             + f3.x * wb[96]  + f3.y * wb[112];
    }
    h2h[(size_t)n * 16 + c] = __float2half(acc);
    float r1 = acc * a_src2[c];
    float r2 = acc * a_dst2[c];
#pragma unroll
    for (int m = 8; m >= 1; m >>= 1) {
        r1 += __shfl_xor_sync(0xffffffffu, r1, m, 16);
        r2 += __shfl_xor_sync(0xffffffffu, r2, m, 16);
    }
    if (c == 0) { asrc2n[n] = r1; adst2n[n] = r2; }
}

// ----- GAT2 pull aggregation + fused GCN transform (h3), unroll x2 -----------
__global__ void k_agg2(const int* __restrict__ rowptr, const int* __restrict__ esrc,
                       const float* __restrict__ asrc, const float* __restrict__ adst,
                       const __half* __restrict__ h2h, const float* __restrict__ b2,
                       const float* __restrict__ W3, __half* __restrict__ gh, int N) {
    __shared__ float W3s[256];
    if (threadIdx.x < 256) W3s[threadIdx.x] = W3[threadIdx.x];
    __syncthreads();
    long long gt = (long long)blockIdx.x * blockDim.x + threadIdx.x;
    int d = (int)(gt >> 2);
    int q = threadIdx.x & 3;
    if (d >= N) return;
    int beg = rowptr[d], endp = rowptr[d + 1];
    float ad = adst[d];
    float den = 0.f;
    float4 acc = {0, 0, 0, 0};
    int idx = beg;
    for (; idx + 1 < endp; idx += 2) {
        int sA = esrc[idx], sB = esrc[idx + 1];
        float wA = __expf(lrelu(asrc[sA] + ad));
        float wB = __expf(lrelu(asrc[sB] + ad));
        den += wA + wB;
        uint2 rA = *reinterpret_cast<const uint2*>(h2h + (size_t)sA * 16 + q * 4);
        uint2 rB = *reinterpret_cast<const uint2*>(h2h + (size_t)sB * 16 + q * 4);
        float2 a0 = __half22float2(*reinterpret_cast<__half2*>(&rA.x));
        float2 a1 = __half22float2(*reinterpret_cast<__half2*>(&rA.y));
        float2 b0 = __half22float2(*reinterpret_cast<__half2*>(&rB.x));
        float2 b1v = __half22float2(*reinterpret_cast<__half2*>(&rB.y));
        acc.x += a0.x * wA + b0.x * wB; acc.y += a0.y * wA + b0.y * wB;
        acc.z += a1.x * wA + b1v.x * wB; acc.w += a1.y * wA + b1v.y * wB;
    }
    if (idx < endp) {
        int s = esrc[idx];
        float wgt = __expf(lrelu(asrc[s] + ad));
        den += wgt;
        uint2 r = *reinterpret_cast<const uint2*>(h2h + (size_t)s * 16 + q * 4);
        float2 f0 = __half22float2(*reinterpret_cast<__half2*>(&r.x));
        float2 f1 = __half22float2(*reinterpret_cast<__half2*>(&r.y));
        acc.x += f0.x * wgt; acc.y += f0.y * wgt;
        acc.z += f1.x * wgt; acc.w += f1.y * wgt;
    }
    float rr = 1.f / den;
    float4 bb = reinterpret_cast<const float4*>(b2)[q];
    float4 o;
    o.x = eluf(acc.x * rr + bb.x); o.y = eluf(acc.y * rr + bb.y);
    o.z = eluf(acc.z * rr + bb.z); o.w = eluf(acc.w * rr + bb.w);

    // ---- fused h3: assemble full 16-vec across the 4-lane group ----
    float v[16];
#pragma unroll
    for (int r = 0; r < 4; r++) {
        v[r * 4 + 0] = __shfl_sync(0xffffffffu, o.x, r, 4);
        v[r * 4 + 1] = __shfl_sync(0xffffffffu, o.y, r, 4);
        v[r * 4 + 2] = __shfl_sync(0xffffffffu, o.z, r, 4);
        v[r * 4 + 3] = __shfl_sync(0xffffffffu, o.w, r, 4);
    }
    float dv = rsqrtf((float)(endp - beg));
    float gacc[4];
#pragma unroll
    for (int j = 0; j < 4; j++) {
        int cc = q * 4 + j;
        float a = 0.f;
#pragma unroll
        for (int k = 0; k < 16; k++) a += v[k] * W3s[k * 16 + cc];
        gacc[j] = a * dv;
    }
    __half2 p0 = __floats2half2_rn(gacc[0], gacc[1]);
    __half2 p1 = __floats2half2_rn(gacc[2], gacc[3]);
    uint2 pk;
    pk.x = *reinterpret_cast<unsigned*>(&p0);
    pk.y = *reinterpret_cast<unsigned*>(&p1);
    *reinterpret_cast<uint2*>(gh + (size_t)d * 16 + q * 4) = pk;
}

// ----- GCN pull aggregation + finalize (fp16 gather), unroll x2 ---------------
__global__ void k_agg3(const int* __restrict__ rowptr, const int* __restrict__ esrc,
                       const __half* __restrict__ gh, const float* __restrict__ b3,
                       float* __restrict__ out, int N) {
    long long gt = (long long)blockIdx.x * blockDim.x + threadIdx.x;
    int d = (int)(gt >> 2);
    int q = threadIdx.x & 3;
    if (d >= N) return;
    int beg = rowptr[d], endp = rowptr[d + 1];
    float4 acc = {0, 0, 0, 0};
    int idx = beg;
    for (; idx + 1 < endp; idx += 2) {
        int sA = esrc[idx], sB = esrc[idx + 1];
        uint2 rA = *reinterpret_cast<const uint2*>(gh + (size_t)sA * 16 + q * 4);
        uint2 rB = *reinterpret_cast<const uint2*>(gh + (size_t)sB * 16 + q * 4);
        float2 a0 = __half22float2(*reinterpret_cast<__half2*>(&rA.x));
        float2 a1 = __half22float2(*reinterpret_cast<__half2*>(&rA.y));
        float2 b0 = __half22float2(*reinterpret_cast<__half2*>(&rB.x));
        float2 b1v = __half22float2(*reinterpret_cast<__half2*>(&rB.y));
        acc.x += a0.x + b0.x; acc.y += a0.y + b0.y;
        acc.z += a1.x + b1v.x; acc.w += a1.y + b1v.y;
    }
    if (idx < endp) {
        int s = esrc[idx];
        uint2 r = *reinterpret_cast<const uint2*>(gh + (size_t)s * 16 + q * 4);
        float2 f0 = __half22float2(*reinterpret_cast<__half2*>(&r.x));
        float2 f1 = __half22float2(*reinterpret_cast<__half2*>(&r.y));
        acc.x += f0.x; acc.y += f0.y; acc.z += f1.x; acc.w += f1.y;
    }
    float dv = rsqrtf((float)(endp - beg));
    float4 bb = reinterpret_cast<const float4*>(b3)[q];
    float4 o;
    o.x = acc.x * dv + bb.x; o.y = acc.y * dv + bb.y;
    o.z = acc.z * dv + bb.z; o.w = acc.w * dv + bb.w;
    reinterpret_cast<float4*>(out + (size_t)d * 16)[q] = o;
}

// ---------------------------------------------------------------------------
extern "C" void kernel_launch(void* const* d_in, const int* in_sizes, int n_in,
                              void* d_out, int out_size) {
    const float* x      = (const float*)d_in[0];
    const int*   ei     = (const int*)d_in[1];
    const float* W1     = (const float*)d_in[2];
    const float* a_src1 = (const float*)d_in[3];
    const float* a_dst1 = (const float*)d_in[4];
    const float* b1     = (const float*)d_in[5];
    const float* W2     = (const float*)d_in[6];
    const float* a_src2 = (const float*)d_in[7];
    const float* a_dst2 = (const float*)d_in[8];
    const float* b2     = (const float*)d_in[9];
    const float* W3     = (const float*)d_in[10];
    const float* b3     = (const float*)d_in[11];
    float* out = (float*)d_out;

    const int N = in_sizes[0] / 128;
    const int E = in_sizes[1] / 2;
    const int ET = E + N;

    float *asrc1, *adst1, *asrc2, *adst2;
    __half *h1h, *out1h, *h2h, *gh, *xh, *xl, *wth, *wtl;
    int *degi, *cursor, *rowptr, *esrc;
    void* p;
    cudaGetSymbolAddress(&p, g_h1h);    h1h    = (__half*)p;
    cudaGetSymbolAddress(&p, g_asrc1);  asrc1  = (float*)p;
    cudaGetSymbolAddress(&p, g_adst1);  adst1  = (float*)p;
    cudaGetSymbolAddress(&p, g_out1h);  out1h  = (__half*)p;
    cudaGetSymbolAddress(&p, g_h2h);    h2h    = (__half*)p;
    cudaGetSymbolAddress(&p, g_asrc2);  asrc2  = (float*)p;
    cudaGetSymbolAddress(&p, g_adst2);  adst2  = (float*)p;
    cudaGetSymbolAddress(&p, g_gh);     gh     = (__half*)p;
    cudaGetSymbolAddress(&p, g_degi);   degi   = (int*)p;
    cudaGetSymbolAddress(&p, g_cursor); cursor = (int*)p;
    cudaGetSymbolAddress(&p, g_rowptr); rowptr = (int*)p;
    cudaGetSymbolAddress(&p, g_esrc);   esrc   = (int*)p;
    cudaGetSymbolAddress(&p, g_xh);     xh     = (__half*)p;
    cudaGetSymbolAddress(&p, g_xl);     xl     = (__half*)p;
    cudaGetSymbolAddress(&p, g_wth);    wth    = (__half*)p;
    cudaGetSymbolAddress(&p, g_wtl);    wtl    = (__half*)p;

    static cudaStream_t s2 = nullptr;
    static cudaEvent_t evFork = nullptr, evJoin = nullptr, evW = nullptr;
    static int smem_set = 0;
    if (!s2) {
        cudaStreamCreateWithFlags(&s2, cudaStreamNonBlocking);
        cudaEventCreateWithFlags(&evFork, cudaEventDisableTiming);
        cudaEventCreateWithFlags(&evJoin, cudaEventDisableTiming);
        cudaEventCreateWithFlags(&evW, cudaEventDisableTiming);
    }
    if (!smem_set) {
        cudaFuncSetAttribute(k_gemm1_tc3,
                             cudaFuncAttributeMaxDynamicSharedMemorySize,
                             SMEM_H * (int)sizeof(__half));
        smem_set = 1;
    }

    const int B = 256;

    // ---- fork: W1 split + CSR chain on s2, concurrent with x split ----
    cudaEventRecord(evFork, 0);
    cudaStreamWaitEvent(s2, evFork, 0);

    k_splitW<<<(256 * 16 + B - 1) / B, B, 0, s2>>>(W1, wth, wtl);
    cudaEventRecord(evW, s2);
    cudaMemsetAsync(degi,   0, (size_t)N * sizeof(int), s2);
    cudaMemsetAsync(cursor, 0, (size_t)N * sizeof(int), s2);
    k_deg<<<(ET + B - 1) / B, B, 0, s2>>>(ei, E, N, degi);
    k_scan<<<1, 1024, 0, s2>>>(degi, rowptr, N, ET);
    k_fill<<<(ET + B - 1) / B, B, 0, s2>>>(ei, E, N, rowptr, cursor, esrc);
    cudaEventRecord(evJoin, s2);

    // main stream: x split, then fp16-split tensor-core GEMM1 (needs wth/wtl)
    k_splitX<<<(N * 16 + B - 1) / B, B>>>(x, xh, xl, N * 16);
    cudaStreamWaitEvent(0, evW, 0);
    {
        dim3 grid((N + 127) / 128, 2);
        k_gemm1_tc3<<<grid, 256, SMEM_H * sizeof(__half)>>>(
            xh, xl, wth, wtl, a_src1, a_dst1, h1h, asrc1, adst1, N);
    }

    // ---- join: agg1 needs CSR ----
    cudaStreamWaitEvent(0, evJoin, 0);

    {
        long long tot = (long long)N * 32;   // warp per dst
        k_agg1<<<(unsigned)((tot + B - 1) / B), B>>>(rowptr, esrc, asrc1, adst1, h1h, b1, out1h, N);
    }

    // Layer 2: GAT(256 -> 16, 1 head)
    k_gemm2<<<(N + 15) / 16, B>>>(out1h, W2, a_src2, a_dst2, h2h, asrc2, adst2, N);
    {
        long long tot = (long long)N * 4;
        k_agg2<<<(unsigned)((tot + B - 1) / B), B>>>(rowptr, esrc, asrc2, adst2, h2h, b2, W3, gh, N);
    }

    // Layer 3: GCN aggregation + finalize
    {
        long long tot = (long long)N * 4;
        k_agg3<<<(unsigned)((tot + B - 1) / B), B>>>(rowptr, esrc, gh, b3, out, N);
    }
}

// round 14
// speedup vs baseline: 2.8852x; 1.1141x over previous
#include <cuda_runtime.h>
#include <cuda_fp16.h>
#include <math.h>

#define NMAX 50000
#define EMAX 800000
#define ETMAX (EMAX + NMAX)

// ---------------- scratch (device globals) -----------------------------------
__device__ __half g_h1h[NMAX * 256];
__device__ float g_asrc1[NMAX * 8];
__device__ float g_adst1[NMAX * 8];
__device__ __half g_out1h[NMAX * 256];
__device__ __half g_h2h[NMAX * 16];
__device__ float g_asrc2[NMAX];
__device__ float g_adst2[NMAX];
__device__ __half g_gh[NMAX * 16];
__device__ int   g_degi[NMAX];
__device__ int   g_cursor[NMAX];
__device__ int   g_rowptr[NMAX + 1];
__device__ int   g_esrc[ETMAX];
__device__ __half g_xh[NMAX * 128];
__device__ __half g_xl[NMAX * 128];
__device__ __half g_wth[256 * 128];
__device__ __half g_wtl[256 * 128];

__device__ __forceinline__ float lrelu(float x) { return x > 0.f ? x : 0.2f * x; }
__device__ __forceinline__ float eluf(float x) { return x > 0.f ? x : expm1f(x); }

// ---------------- CSR build ---------------------------------------------------
__global__ void k_deg(const int* __restrict__ ei, int E, int N, int* __restrict__ degi) {
    int e = blockIdx.x * blockDim.x + threadIdx.x;
    int ET = E + N;
    if (e >= ET) return;
    int d = (e < E) ? ei[E + e] : e - E;
    atomicAdd(&degi[d], 1);
}

// coalesced tiled exclusive scan (single block, 1024 threads)
__global__ void k_scan(const int* __restrict__ degi, int* __restrict__ rowptr,
                       int N, int ET) {
    __shared__ int warpsum[32];
    __shared__ int carry;
    int t = threadIdx.x;
    int lane = t & 31, wid = t >> 5;
    if (t == 0) carry = 0;
    __syncthreads();
    for (int base = 0; base < N; base += 1024) {
        int i = base + t;
        int v = (i < N) ? degi[i] : 0;
        int s = v;
#pragma unroll
        for (int off = 1; off < 32; off <<= 1) {
            int u = __shfl_up_sync(0xffffffffu, s, off);
            if (lane >= off) s += u;
        }
        if (lane == 31) warpsum[wid] = s;
        __syncthreads();
        if (wid == 0) {
            int ws = warpsum[lane];
#pragma unroll
            for (int off = 1; off < 32; off <<= 1) {
                int u = __shfl_up_sync(0xffffffffu, ws, off);
                if (lane >= off) ws += u;
            }
            warpsum[lane] = ws;
        }
        __syncthreads();
        int woff = (wid == 0) ? 0 : warpsum[wid - 1];
        int excl = carry + woff + s - v;
        if (i < N) rowptr[i] = excl;
        __syncthreads();
        if (t == 0) carry += warpsum[31];
        __syncthreads();
    }
    if (t == 0) rowptr[N] = ET;
}

__global__ void k_fill(const int* __restrict__ ei, int E, int N,
                       const int* __restrict__ rowptr, int* __restrict__ cursor,
                       int* __restrict__ esrc) {
    int e = blockIdx.x * blockDim.x + threadIdx.x;
    int ET = E + N;
    if (e >= ET) return;
    int s, d;
    if (e < E) { s = ei[e]; d = ei[E + e]; } else { s = d = e - E; }
    int pos = rowptr[d] + atomicAdd(&cursor[d], 1);
    esrc[pos] = s;
}

// ---------------- helpers ------------------------------------------------------
__device__ __forceinline__ void mma_f16(float* d, const unsigned* a, const unsigned* b) {
    asm volatile("mma.sync.aligned.m16n8k16.row.col.f32.f16.f16.f32 "
                 "{%0,%1,%2,%3}, {%4,%5,%6,%7}, {%8,%9}, {%0,%1,%2,%3};"
                 : "+f"(d[0]), "+f"(d[1]), "+f"(d[2]), "+f"(d[3])
                 : "r"(a[0]), "r"(a[1]), "r"(a[2]), "r"(a[3]),
                   "r"(b[0]), "r"(b[1]));
}

__device__ __forceinline__ void cpasync16(void* dst, const void* src) {
    unsigned d = (unsigned)__cvta_generic_to_shared(dst);
    asm volatile("cp.async.cg.shared.global [%0], [%1], 16;" :: "r"(d), "l"(src));
}

__device__ __forceinline__ void f16split(float x, __half& hi, __half& lo) {
    hi = __float2half_rn(x);
    lo = __float2half_rn(x - __half2float(hi));
}

// ---------------- split X: f32 -> hi/lo fp16 planes ---------------------------
__global__ void k_splitX(const float* __restrict__ src, __half* __restrict__ dh,
                         __half* __restrict__ dl, int total8) {
    int i = blockIdx.x * blockDim.x + threadIdx.x;
    if (i >= total8) return;
    const float4* s4 = reinterpret_cast<const float4*>(src) + (size_t)i * 2;
    float4 v0 = s4[0], v1 = s4[1];
    __half h[8], l[8];
    f16split(v0.x, h[0], l[0]); f16split(v0.y, h[1], l[1]);
    f16split(v0.z, h[2], l[2]); f16split(v0.w, h[3], l[3]);
    f16split(v1.x, h[4], l[4]); f16split(v1.y, h[5], l[5]);
    f16split(v1.z, h[6], l[6]); f16split(v1.w, h[7], l[7]);
    *reinterpret_cast<uint4*>(dh + (size_t)i * 8) = *reinterpret_cast<uint4*>(h);
    *reinterpret_cast<uint4*>(dl + (size_t)i * 8) = *reinterpret_cast<uint4*>(l);
}

// ---------------- split + transpose W1 ----------------------------------------
__global__ void k_splitW(const float* __restrict__ W1, __half* __restrict__ dh,
                         __half* __restrict__ dl) {
    int i = blockIdx.x * blockDim.x + threadIdx.x;
    if (i >= 256 * 16) return;
    int n = i >> 4, kq = i & 15;
    __half h[8], l[8];
#pragma unroll
    for (int j = 0; j < 8; j++)
        f16split(W1[(kq * 8 + j) * 256 + n], h[j], l[j]);
    *reinterpret_cast<uint4*>(dh + (size_t)n * 128 + kq * 8) = *reinterpret_cast<uint4*>(h);
    *reinterpret_cast<uint4*>(dl + (size_t)n * 128 + kq * 8) = *reinterpret_cast<uint4*>(l);
}

// ---------------- GEMM1 (fp16 2-term split, m16n8k16, fused alpha) ------------
#define ASTR 24
#define PL   (128 * ASTR)
#define STG  (4 * PL)
#define SMEM_H (2 * STG)

__global__ __launch_bounds__(256) void k_gemm1_tc3(
        const __half* __restrict__ xh, const __half* __restrict__ xl,
        const __half* __restrict__ wth, const __half* __restrict__ wtl,
        const float* __restrict__ a_src, const float* __restrict__ a_dst,
        __half* __restrict__ h1h, float* __restrict__ asrcn, float* __restrict__ adstn,
        int N) {
    extern __shared__ __half smh[];
    const int t = threadIdx.x;
    const int warp = t >> 5, lane = t & 31;
    const int wm = warp >> 2, wn = warp & 3;
    const int lm = lane >> 2, lk = lane & 3;
    const int r0 = blockIdx.x * 128;
    const int n0 = blockIdx.y * 128;

    float acc[4][4][4];
#pragma unroll
    for (int i = 0; i < 4; i++)
#pragma unroll
        for (int j = 0; j < 4; j++)
#pragma unroll
            for (int v = 0; v < 4; v++) acc[i][j][v] = 0.f;

    auto issue = [&](int c, int buf) {
        int k0 = c * 16;
        __half* base = smh + buf * STG;
        int row = t >> 1, seg = t & 1;
        int gr = r0 + row; if (gr > N - 1) gr = N - 1;
        cpasync16(base + row * ASTR + seg * 8,
                  xh + (size_t)gr * 128 + k0 + seg * 8);
        cpasync16(base + PL + row * ASTR + seg * 8,
                  xl + (size_t)gr * 128 + k0 + seg * 8);
        cpasync16(base + 2 * PL + row * ASTR + seg * 8,
                  wth + (size_t)(n0 + row) * 128 + k0 + seg * 8);
        cpasync16(base + 3 * PL + row * ASTR + seg * 8,
                  wtl + (size_t)(n0 + row) * 128 + k0 + seg * 8);
        asm volatile("cp.async.commit_group;");
    };

    issue(0, 0);
    for (int c = 0; c < 8; c++) {
        int buf = c & 1;
        if (c < 7) {
            issue(c + 1, buf ^ 1);
            asm volatile("cp.async.wait_group 1;");
        } else {
            asm volatile("cp.async.wait_group 0;");
        }
        __syncthreads();
        const __half* Ah = smh + buf * STG;
        const __half* Al = Ah + PL;
        const __half* Bh = Ah + 2 * PL;
        const __half* Bl = Ah + 3 * PL;
        const int kb = lk * 2;

        unsigned Ahf[4][4], Alf[4][4];
#pragma unroll
        for (int mt = 0; mt < 4; mt++) {
            int mrow = wm * 64 + mt * 16 + lm;
            Ahf[mt][0] = *reinterpret_cast<const unsigned*>(Ah + mrow * ASTR + kb);
            Ahf[mt][1] = *reinterpret_cast<const unsigned*>(Ah + (mrow + 8) * ASTR + kb);
            Ahf[mt][2] = *reinterpret_cast<const unsigned*>(Ah + mrow * ASTR + kb + 8);
            Ahf[mt][3] = *reinterpret_cast<const unsigned*>(Ah + (mrow + 8) * ASTR + kb + 8);
            Alf[mt][0] = *reinterpret_cast<const unsigned*>(Al + mrow * ASTR + kb);
            Alf[mt][1] = *reinterpret_cast<const unsigned*>(Al + (mrow + 8) * ASTR + kb);
            Alf[mt][2] = *reinterpret_cast<const unsigned*>(Al + mrow * ASTR + kb + 8);
            Alf[mt][3] = *reinterpret_cast<const unsigned*>(Al + (mrow + 8) * ASTR + kb + 8);
        }
        unsigned Bhf[4][2], Blf[4][2];
#pragma unroll
        for (int nt = 0; nt < 4; nt++) {
            int n = wn * 32 + nt * 8 + lm;
            Bhf[nt][0] = *reinterpret_cast<const unsigned*>(Bh + n * ASTR + kb);
            Bhf[nt][1] = *reinterpret_cast<const unsigned*>(Bh + n * ASTR + kb + 8);
            Blf[nt][0] = *reinterpret_cast<const unsigned*>(Bl + n * ASTR + kb);
            Blf[nt][1] = *reinterpret_cast<const unsigned*>(Bl + n * ASTR + kb + 8);
        }
#pragma unroll
        for (int mt = 0; mt < 4; mt++)
#pragma unroll
            for (int nt = 0; nt < 4; nt++) {
                mma_f16(acc[mt][nt], Ahf[mt], Bhf[nt]);
                mma_f16(acc[mt][nt], Ahf[mt], Blf[nt]);
                mma_f16(acc[mt][nt], Alf[mt], Bhf[nt]);
            }
        __syncthreads();
    }

    const int h = blockIdx.y * 4 + wn;
    float2 asv[4], adv[4];
#pragma unroll
    for (int nt = 0; nt < 4; nt++) {
        asv[nt] = *reinterpret_cast<const float2*>(a_src + h * 32 + nt * 8 + lk * 2);
        adv[nt] = *reinterpret_cast<const float2*>(a_dst + h * 32 + nt * 8 + lk * 2);
    }
#pragma unroll
    for (int mt = 0; mt < 4; mt++) {
        int row1 = r0 + wm * 64 + mt * 16 + lm;
        int row2 = row1 + 8;
        float s1 = 0.f, d1 = 0.f, s2 = 0.f, d2 = 0.f;
#pragma unroll
        for (int nt = 0; nt < 4; nt++) {
            int col = n0 + wn * 32 + nt * 8 + lk * 2;
            s1 += acc[mt][nt][0] * asv[nt].x + acc[mt][nt][1] * asv[nt].y;
            d1 += acc[mt][nt][0] * adv[nt].x + acc[mt][nt][1] * adv[nt].y;
            s2 += acc[mt][nt][2] * asv[nt].x + acc[mt][nt][3] * asv[nt].y;
            d2 += acc[mt][nt][2] * adv[nt].x + acc[mt][nt][3] * adv[nt].y;
            if (row1 < N)
                *reinterpret_cast<__half2*>(h1h + (size_t)row1 * 256 + col) =
                    __floats2half2_rn(acc[mt][nt][0], acc[mt][nt][1]);
            if (row2 < N)
                *reinterpret_cast<__half2*>(h1h + (size_t)row2 * 256 + col) =
                    __floats2half2_rn(acc[mt][nt][2], acc[mt][nt][3]);
        }
        s1 += __shfl_xor_sync(0xffffffffu, s1, 1); s1 += __shfl_xor_sync(0xffffffffu, s1, 2);
        d1 += __shfl_xor_sync(0xffffffffu, d1, 1); d1 += __shfl_xor_sync(0xffffffffu, d1, 2);
        s2 += __shfl_xor_sync(0xffffffffu, s2, 1); s2 += __shfl_xor_sync(0xffffffffu, s2, 2);
        d2 += __shfl_xor_sync(0xffffffffu, d2, 1); d2 += __shfl_xor_sync(0xffffffffu, d2, 2);
        if (lk == 0) {
            if (row1 < N) { asrcn[row1 * 8 + h] = s1; adstn[row1 * 8 + h] = d1; }
            if (row2 < N) { asrcn[row2 * 8 + h] = s2; adstn[row2 * 8 + h] = d2; }
        }
    }
}

// ----- GAT1 pull aggregation: warp per dst, per-lane head weights, unroll x4 --
__global__ void k_agg1(const int* __restrict__ rowptr, const int* __restrict__ esrc,
                       const float* __restrict__ asrc, const float* __restrict__ adst,
                       const __half* __restrict__ h1h, const float* __restrict__ b1,
                       __half* __restrict__ out1h, int N) {
    int d = (int)(((long long)blockIdx.x * blockDim.x + threadIdx.x) >> 5);
    int lane = threadIdx.x & 31;
    if (d >= N) return;
    int beg = rowptr[d], endp = rowptr[d + 1];
    const int h0 = lane >> 2;
    float ad = adst[d * 8 + h0];
    float den = 0.f;
    float accv[8];
#pragma unroll
    for (int i = 0; i < 8; i++) accv[i] = 0.f;
    for (int base = beg; base < endp; base += 32) {
        int nn = min(32, endp - base);
        int sreg = (base + lane < endp) ? esrc[base + lane] : 0;
        int j = 0;
        for (; j + 3 < nn; j += 4) {
            int s0 = __shfl_sync(0xffffffffu, sreg, j);
            int s1 = __shfl_sync(0xffffffffu, sreg, j + 1);
            int s2 = __shfl_sync(0xffffffffu, sreg, j + 2);
            int s3 = __shfl_sync(0xffffffffu, sreg, j + 3);
            float w0 = __expf(lrelu(asrc[s0 * 8 + h0] + ad));
            float w1 = __expf(lrelu(asrc[s1 * 8 + h0] + ad));
            float w2 = __expf(lrelu(asrc[s2 * 8 + h0] + ad));
            float w3 = __expf(lrelu(asrc[s3 * 8 + h0] + ad));
            den += (w0 + w1) + (w2 + w3);
            uint4 r0 = *reinterpret_cast<const uint4*>(h1h + (size_t)s0 * 256 + lane * 8);
            uint4 r1 = *reinterpret_cast<const uint4*>(h1h + (size_t)s1 * 256 + lane * 8);
            uint4 r2 = *reinterpret_cast<const uint4*>(h1h + (size_t)s2 * 256 + lane * 8);
            uint4 r3 = *reinterpret_cast<const uint4*>(h1h + (size_t)s3 * 256 + lane * 8);
            {
                float2 f0 = __half22float2(*reinterpret_cast<__half2*>(&r0.x));
                float2 f1 = __half22float2(*reinterpret_cast<__half2*>(&r0.y));
                float2 f2 = __half22float2(*reinterpret_cast<__half2*>(&r0.z));
                float2 f3 = __half22float2(*reinterpret_cast<__half2*>(&r0.w));
                accv[0] += f0.x * w0; accv[1] += f0.y * w0;
                accv[2] += f1.x * w0; accv[3] += f1.y * w0;
                accv[4] += f2.x * w0; accv[5] += f2.y * w0;
                accv[6] += f3.x * w0; accv[7] += f3.y * w0;
            }
            {
                float2 f0 = __half22float2(*reinterpret_cast<__half2*>(&r1.x));
                float2 f1 = __half22float2(*reinterpret_cast<__half2*>(&r1.y));
                float2 f2 = __half22float2(*reinterpret_cast<__half2*>(&r1.z));
                float2 f3 = __half22float2(*reinterpret_cast<__half2*>(&r1.w));
                accv[0] += f0.x * w1; accv[1] += f0.y * w1;
                accv[2] += f1.x * w1; accv[3] += f1.y * w1;
                accv[4] += f2.x * w1; accv[5] += f2.y * w1;
                accv[6] += f3.x * w1; accv[7] += f3.y * w1;
            }
            {
                float2 f0 = __half22float2(*reinterpret_cast<__half2*>(&r2.x));
                float2 f1 = __half22float2(*reinterpret_cast<__half2*>(&r2.y));
                float2 f2 = __half22float2(*reinterpret_cast<__half2*>(&r2.z));
                float2 f3 = __half22float2(*reinterpret_cast<__half2*>(&r2.w));
                accv[0] += f0.x * w2; accv[1] += f0.y * w2;
                accv[2] += f1.x * w2; accv[3] += f1.y * w2;
                accv[4] += f2.x * w2; accv[5] += f2.y * w2;
                accv[6] += f3.x * w2; accv[7] += f3.y * w2;
            }
            {
                float2 f0 = __half22float2(*reinterpret_cast<__half2*>(&r3.x));
                float2 f1 = __half22float2(*reinterpret_cast<__half2*>(&r3.y));
                float2 f2 = __half22float2(*reinterpret_cast<__half2*>(&r3.z));
                float2 f3 = __half22float2(*reinterpret_cast<__half2*>(&r3.w));
                accv[0] += f0.x * w3; accv[1] += f0.y * w3;
                accv[2] += f1.x * w3; accv[3] += f1.y * w3;
                accv[4] += f2.x * w3; accv[5] += f2.y * w3;
                accv[6] += f3.x * w3; accv[7] += f3.y * w3;
            }
        }
        for (; j < nn; j++) {
            int s = __shfl_sync(0xffffffffu, sreg, j);
            float a = __expf(lrelu(asrc[s * 8 + h0] + ad));
            den += a;
            uint4 r = *reinterpret_cast<const uint4*>(h1h + (size_t)s * 256 + lane * 8);
            float2 f0 = __half22float2(*reinterpret_cast<__half2*>(&r.x));
            float2 f1 = __half22float2(*reinterpret_cast<__half2*>(&r.y));
            float2 f2 = __half22float2(*reinterpret_cast<__half2*>(&r.z));
            float2 f3 = __half22float2(*reinterpret_cast<__half2*>(&r.w));
            accv[0] += f0.x * a; accv[1] += f0.y * a;
            accv[2] += f1.x * a; accv[3] += f1.y * a;
            accv[4] += f2.x * a; accv[5] += f2.y * a;
            accv[6] += f3.x * a; accv[7] += f3.y * a;
        }
    }
    float rs = 1.f / den;
    const float4* bp = reinterpret_cast<const float4*>(b1 + lane * 8);
    float4 bb0 = bp[0], bb1 = bp[1];
    float o[8];
    o[0] = eluf(accv[0] * rs + bb0.x); o[1] = eluf(accv[1] * rs + bb0.y);
    o[2] = eluf(accv[2] * rs + bb0.z); o[3] = eluf(accv[3] * rs + bb0.w);
    o[4] = eluf(accv[4] * rs + bb1.x); o[5] = eluf(accv[5] * rs + bb1.y);
    o[6] = eluf(accv[6] * rs + bb1.z); o[7] = eluf(accv[7] * rs + bb1.w);
    __half2 p0 = __floats2half2_rn(o[0], o[1]);
    __half2 p1 = __floats2half2_rn(o[2], o[3]);
    __half2 p2 = __floats2half2_rn(o[4], o[5]);
    __half2 p3 = __floats2half2_rn(o[6], o[7]);
    uint4 pk;
    pk.x = *reinterpret_cast<unsigned*>(&p0);
    pk.y = *reinterpret_cast<unsigned*>(&p1);
    pk.z = *reinterpret_cast<unsigned*>(&p2);
    pk.w = *reinterpret_cast<unsigned*>(&p3);
    *reinterpret_cast<uint4*>(out1h + (size_t)d * 256 + lane * 8) = pk;
}

// ----- GEMM2: h2 = x2[N,256] @ W2[256,16], fp16 in (uint4), fused alpha2 -----
__global__ void k_gemm2(const __half* __restrict__ x2h, const float* __restrict__ W2,
                        const float* __restrict__ a_src2, const float* __restrict__ a_dst2,
                        __half* __restrict__ h2h, float* __restrict__ asrc2n,
                        float* __restrict__ adst2n, int N) {
    __shared__ float Wsh[256 * 16];
    int t = threadIdx.x;
    for (int i = t; i < 4096; i += 256) Wsh[i] = W2[i];
    __syncthreads();
    int n = blockIdx.x * 16 + (t >> 4);
    int c = t & 15;
    if (n >= N) return;
    float acc = 0.f;
    const uint4* xr4 = reinterpret_cast<const uint4*>(x2h + (size_t)n * 256);
#pragma unroll 8
    for (int kq = 0; kq < 32; kq++) {
        uint4 r = xr4[kq];
        float2 f0 = __half22float2(*reinterpret_cast<__half2*>(&r.x));
        float2 f1 = __half22float2(*reinterpret_cast<__half2*>(&r.y));
        float2 f2 = __half22float2(*reinterpret_cast<__half2*>(&r.z));
        float2 f3 = __half22float2(*reinterpret_cast<__half2*>(&r.w));
        const float* wb = Wsh + (kq * 8) * 16 + c;
        acc += f0.x * wb[0]   + f0.y * wb[16]
             + f1.x * wb[32]  + f1.y * wb[48]
             + f2.x * wb[64]  + f2.y * wb[80]
             + f3.x * wb[96]  + f3.y * wb[112];
    }
    h2h[(size_t)n * 16 + c] = __float2half(acc);
    float r1 = acc * a_src2[c];
    float r2 = acc * a_dst2[c];
#pragma unroll
    for (int m = 8; m >= 1; m >>= 1) {
        r1 += __shfl_xor_sync(0xffffffffu, r1, m, 16);
        r2 += __shfl_xor_sync(0xffffffffu, r2, m, 16);
    }
    if (c == 0) { asrc2n[n] = r1; adst2n[n] = r2; }
}

// ----- GAT2 pull aggregation + fused GCN transform (h3), unroll x2 -----------
__global__ void k_agg2(const int* __restrict__ rowptr, const int* __restrict__ esrc,
                       const float* __restrict__ asrc, const float* __restrict__ adst,
                       const __half* __restrict__ h2h, const float* __restrict__ b2,
                       const float* __restrict__ W3, __half* __restrict__ gh, int N) {
    __shared__ float W3s[256];
    if (threadIdx.x < 256) W3s[threadIdx.x] = W3[threadIdx.x];
    __syncthreads();
    long long gt = (long long)blockIdx.x * blockDim.x + threadIdx.x;
    int d = (int)(gt >> 2);
    int q = threadIdx.x & 3;
    if (d >= N) return;
    int beg = rowptr[d], endp = rowptr[d + 1];
    float ad = adst[d];
    float den = 0.f;
    float4 acc = {0, 0, 0, 0};
    int idx = beg;
    for (; idx + 1 < endp; idx += 2) {
        int sA = esrc[idx], sB = esrc[idx + 1];
        float wA = __expf(lrelu(asrc[sA] + ad));
        float wB = __expf(lrelu(asrc[sB] + ad));
        den += wA + wB;
        uint2 rA = *reinterpret_cast<const uint2*>(h2h + (size_t)sA * 16 + q * 4);
        uint2 rB = *reinterpret_cast<const uint2*>(h2h + (size_t)sB * 16 + q * 4);
        float2 a0 = __half22float2(*reinterpret_cast<__half2*>(&rA.x));
        float2 a1 = __half22float2(*reinterpret_cast<__half2*>(&rA.y));
        float2 b0 = __half22float2(*reinterpret_cast<__half2*>(&rB.x));
        float2 b1v = __half22float2(*reinterpret_cast<__half2*>(&rB.y));
        acc.x += a0.x * wA + b0.x * wB; acc.y += a0.y * wA + b0.y * wB;
        acc.z += a1.x * wA + b1v.x * wB; acc.w += a1.y * wA + b1v.y * wB;
    }
    if (idx < endp) {
        int s = esrc[idx];
        float wgt = __expf(lrelu(asrc[s] + ad));
        den += wgt;
        uint2 r = *reinterpret_cast<const uint2*>(h2h + (size_t)s * 16 + q * 4);
        float2 f0 = __half22float2(*reinterpret_cast<__half2*>(&r.x));
        float2 f1 = __half22float2(*reinterpret_cast<__half2*>(&r.y));
        acc.x += f0.x * wgt; acc.y += f0.y * wgt;
        acc.z += f1.x * wgt; acc.w += f1.y * wgt;
    }
    float rr = 1.f / den;
    float4 bb = reinterpret_cast<const float4*>(b2)[q];
    float4 o;
    o.x = eluf(acc.x * rr + bb.x); o.y = eluf(acc.y * rr + bb.y);
    o.z = eluf(acc.z * rr + bb.z); o.w = eluf(acc.w * rr + bb.w);

    float v[16];
#pragma unroll
    for (int r = 0; r < 4; r++) {
        v[r * 4 + 0] = __shfl_sync(0xffffffffu, o.x, r, 4);
        v[r * 4 + 1] = __shfl_sync(0xffffffffu, o.y, r, 4);
        v[r * 4 + 2] = __shfl_sync(0xffffffffu, o.z, r, 4);
        v[r * 4 + 3] = __shfl_sync(0xffffffffu, o.w, r, 4);
    }
    float dv = rsqrtf((float)(endp - beg));
    float gacc[4];
#pragma unroll
    for (int j = 0; j < 4; j++) {
        int cc = q * 4 + j;
        float a = 0.f;
#pragma unroll
        for (int k = 0; k < 16; k++) a += v[k] * W3s[k * 16 + cc];
        gacc[j] = a * dv;
    }
    __half2 p0 = __floats2half2_rn(gacc[0], gacc[1]);
    __half2 p1 = __floats2half2_rn(gacc[2], gacc[3]);
    uint2 pk;
    pk.x = *reinterpret_cast<unsigned*>(&p0);
    pk.y = *reinterpret_cast<unsigned*>(&p1);
    *reinterpret_cast<uint2*>(gh + (size_t)d * 16 + q * 4) = pk;
}

// ----- GCN pull aggregation + finalize (fp16 gather), unroll x2 ---------------
__global__ void k_agg3(const int* __restrict__ rowptr, const int* __restrict__ esrc,
                       const __half* __restrict__ gh, const float* __restrict__ b3,
                       float* __restrict__ out, int N) {
    long long gt = (long long)blockIdx.x * blockDim.x + threadIdx.x;
    int d = (int)(gt >> 2);
    int q = threadIdx.x & 3;
    if (d >= N) return;
    int beg = rowptr[d], endp = rowptr[d + 1];
    float4 acc = {0, 0, 0, 0};
    int idx = beg;
    for (; idx + 1 < endp; idx += 2) {
        int sA = esrc[idx], sB = esrc[idx + 1];
        uint2 rA = *reinterpret_cast<const uint2*>(gh + (size_t)sA * 16 + q * 4);
        uint2 rB = *reinterpret_cast<const uint2*>(gh + (size_t)sB * 16 + q * 4);
        float2 a0 = __half22float2(*reinterpret_cast<__half2*>(&rA.x));
        float2 a1 = __half22float2(*reinterpret_cast<__half2*>(&rA.y));
        float2 b0 = __half22float2(*reinterpret_cast<__half2*>(&rB.x));
        float2 b1v = __half22float2(*reinterpret_cast<__half2*>(&rB.y));
        acc.x += a0.x + b0.x; acc.y += a0.y + b0.y;
        acc.z += a1.x + b1v.x; acc.w += a1.y + b1v.y;
    }
    if (idx < endp) {
        int s = esrc[idx];
        uint2 r = *reinterpret_cast<const uint2*>(gh + (size_t)s * 16 + q * 4);
        float2 f0 = __half22float2(*reinterpret_cast<__half2*>(&r.x));
        float2 f1 = __half22float2(*reinterpret_cast<__half2*>(&r.y));
        acc.x += f0.x; acc.y += f0.y; acc.z += f1.x; acc.w += f1.y;
    }
    float dv = rsqrtf((float)(endp - beg));
    float4 bb = reinterpret_cast<const float4*>(b3)[q];
    float4 o;
    o.x = acc.x * dv + bb.x; o.y = acc.y * dv + bb.y;
    o.z = acc.z * dv + bb.z; o.w = acc.w * dv + bb.w;
    reinterpret_cast<float4*>(out + (size_t)d * 16)[q] = o;
}

// ---------------------------------------------------------------------------
extern "C" void kernel_launch(void* const* d_in, const int* in_sizes, int n_in,
                              void* d_out, int out_size) {
    const float* x      = (const float*)d_in[0];
    const int*   ei     = (const int*)d_in[1];
    const float* W1     = (const float*)d_in[2];
    const float* a_src1 = (const float*)d_in[3];
    const float* a_dst1 = (const float*)d_in[4];
    const float* b1     = (const float*)d_in[5];
    const float* W2     = (const float*)d_in[6];
    const float* a_src2 = (const float*)d_in[7];
    const float* a_dst2 = (const float*)d_in[8];
    const float* b2     = (const float*)d_in[9];
    const float* W3     = (const float*)d_in[10];
    const float* b3     = (const float*)d_in[11];
    float* out = (float*)d_out;

    const int N = in_sizes[0] / 128;
    const int E = in_sizes[1] / 2;
    const int ET = E + N;

    float *asrc1, *adst1, *asrc2, *adst2;
    __half *h1h, *out1h, *h2h, *gh, *xh, *xl, *wth, *wtl;
    int *degi, *cursor, *rowptr, *esrc;
    void* p;
    cudaGetSymbolAddress(&p, g_h1h);    h1h    = (__half*)p;
    cudaGetSymbolAddress(&p, g_asrc1);  asrc1  = (float*)p;
    cudaGetSymbolAddress(&p, g_adst1);  adst1  = (float*)p;
    cudaGetSymbolAddress(&p, g_out1h);  out1h  = (__half*)p;
    cudaGetSymbolAddress(&p, g_h2h);    h2h    = (__half*)p;
    cudaGetSymbolAddress(&p, g_asrc2);  asrc2  = (float*)p;
    cudaGetSymbolAddress(&p, g_adst2);  adst2  = (float*)p;
    cudaGetSymbolAddress(&p, g_gh);     gh     = (__half*)p;
    cudaGetSymbolAddress(&p, g_degi);   degi   = (int*)p;
    cudaGetSymbolAddress(&p, g_cursor); cursor = (int*)p;
    cudaGetSymbolAddress(&p, g_rowptr); rowptr = (int*)p;
    cudaGetSymbolAddress(&p, g_esrc);   esrc   = (int*)p;
    cudaGetSymbolAddress(&p, g_xh);     xh     = (__half*)p;
    cudaGetSymbolAddress(&p, g_xl);     xl     = (__half*)p;
    cudaGetSymbolAddress(&p, g_wth);    wth    = (__half*)p;
    cudaGetSymbolAddress(&p, g_wtl);    wtl    = (__half*)p;

    static cudaStream_t s2 = nullptr;
    static cudaEvent_t evFork = nullptr, evJoin = nullptr, evW = nullptr;
    static int smem_set = 0;
    if (!s2) {
        cudaStreamCreateWithFlags(&s2, cudaStreamNonBlocking);
        cudaEventCreateWithFlags(&evFork, cudaEventDisableTiming);
        cudaEventCreateWithFlags(&evJoin, cudaEventDisableTiming);
        cudaEventCreateWithFlags(&evW, cudaEventDisableTiming);
    }
    if (!smem_set) {
        cudaFuncSetAttribute(k_gemm1_tc3,
                             cudaFuncAttributeMaxDynamicSharedMemorySize,
                             SMEM_H * (int)sizeof(__half));
        smem_set = 1;
    }

    const int B = 256;

    // ---- fork: W1 split + CSR chain on s2, concurrent with x split ----
    cudaEventRecord(evFork, 0);
    cudaStreamWaitEvent(s2, evFork, 0);

    k_splitW<<<(256 * 16 + B - 1) / B, B, 0, s2>>>(W1, wth, wtl);
    cudaEventRecord(evW, s2);
    cudaMemsetAsync(degi,   0, (size_t)N * sizeof(int), s2);
    cudaMemsetAsync(cursor, 0, (size_t)N * sizeof(int), s2);
    k_deg<<<(ET + B - 1) / B, B, 0, s2>>>(ei, E, N, degi);
    k_scan<<<1, 1024, 0, s2>>>(degi, rowptr, N, ET);
    k_fill<<<(ET + B - 1) / B, B, 0, s2>>>(ei, E, N, rowptr, cursor, esrc);
    cudaEventRecord(evJoin, s2);

    // main stream: x split, then fp16-split tensor-core GEMM1 (needs wth/wtl)
    k_splitX<<<(N * 16 + B - 1) / B, B>>>(x, xh, xl, N * 16);
    cudaStreamWaitEvent(0, evW, 0);
    {
        dim3 grid((N + 127) / 128, 2);
        k_gemm1_tc3<<<grid, 256, SMEM_H * sizeof(__half)>>>(
            xh, xl, wth, wtl, a_src1, a_dst1, h1h, asrc1, adst1, N);
    }

    // ---- join: agg1 needs CSR ----
    cudaStreamWaitEvent(0, evJoin, 0);

    {
        long long tot = (long long)N * 32;   // warp per dst
        k_agg1<<<(unsigned)((tot + B - 1) / B), B>>>(rowptr, esrc, asrc1, adst1, h1h, b1, out1h, N);
    }

    // Layer 2: GAT(256 -> 16, 1 head)
    k_gemm2<<<(N + 15) / 16, B>>>(out1h, W2, a_src2, a_dst2, h2h, asrc2, adst2, N);
    {
        long long tot = (long long)N * 4;
        k_agg2<<<(unsigned)((tot + B - 1) / B), B>>>(rowptr, esrc, asrc2, adst2, h2h, b2, W3, gh, N);
    }

    // Layer 3: GCN aggregation + finalize
    {
        long long tot = (long long)N * 4;
        k_agg3<<<(unsigned)((tot + B - 1) / B), B>>>(rowptr, esrc, gh, b3, out, N);
    }
}